// round 13
// baseline (speedup 1.0000x reference)
#include <cuda_runtime.h>
#include <cuda_bf16.h>
#include <cstdint>

#define NH 4
#define DIMC 128
#define BT_N 2209   // 47^2

// Per-pixel layouts (rolled space): 32768 rows x 128.
__device__ __align__(16) float g_Q [32768 * DIMC];
__device__ __align__(16) float g_K [32768 * DIMC];
__device__ __align__(16) float g_V [32768 * DIMC];
__device__ __align__(16) float g_AO[32768 * DIMC];

__device__ __forceinline__ float ex2f(float x) {
    float r; asm("ex2.approx.f32 %0,%1;" : "=f"(r) : "f"(x)); return r;
}
__device__ __forceinline__ int reflect_idx(int p, int n) {
    if (p < 0) p = -p;
    else if (p >= n) p = 2 * n - 2 - p;
    return p;
}
// Split (a,b) into packed bf16 hi (returned; a in low half) and packed lo remainder.
__device__ __forceinline__ uint32_t bfsplit(float a, float b, uint32_t& lo) {
    uint32_t hi;
    asm("cvt.rn.bf16x2.f32 %0,%1,%2;" : "=r"(hi) : "f"(b), "f"(a));
    float ra = __uint_as_float(hi << 16);
    float rb = __uint_as_float(hi & 0xffff0000u);
    asm("cvt.rn.bf16x2.f32 %0,%1,%2;" : "=r"(lo) : "f"(b - rb), "f"(a - ra));
    return hi;
}

// mma.sync m16n8k16 bf16: D(f32x4) += A(4xb32) * B(2xb32)   (sm_80+, non-'a')
__device__ __forceinline__ void mma_bf16(float d[4], const uint32_t a[4], const uint32_t b[2]) {
    asm volatile(
        "mma.sync.aligned.m16n8k16.row.col.f32.bf16.bf16.f32 "
        "{%0,%1,%2,%3},{%4,%5,%6,%7},{%8,%9},{%0,%1,%2,%3};"
        : "+f"(d[0]), "+f"(d[1]), "+f"(d[2]), "+f"(d[3])
        : "r"(a[0]), "r"(a[1]), "r"(a[2]), "r"(a[3]), "r"(b[0]), "r"(b[1]));
}

// ---------------------------------------------------------------------------
// Split-bf16 MMA projection GEMM (passing, unchanged).
// ---------------------------------------------------------------------------
#define XS_STRIDE 132
#define WS_STRIDE 68
#define PROJ_SMEM (64 * XS_STRIDE * 4 + 2 * 128 * WS_STRIDE * 4)   // 103424

struct ProjSmem {
    float* xs;
    uint32_t* whi;
    uint32_t* wlo;
};
__device__ __forceinline__ ProjSmem proj_smem(char* smraw) {
    ProjSmem p;
    p.xs  = (float*)smraw;
    p.whi = (uint32_t*)(smraw + 64 * XS_STRIDE * 4);
    p.wlo = p.whi + 128 * WS_STRIDE;
    return p;
}

__device__ __forceinline__ void stage_W(ProjSmem& sm, const float* __restrict__ W, int t) {
    #pragma unroll
    for (int it = 0; it < 32; it++) {
        int e  = t + it * 256;
        int c  = e >> 6;
        int kp = e & 63;
        float2 wv = ((const float2*)W)[c * 64 + kp];
        uint32_t lo, hi = bfsplit(wv.x, wv.y, lo);
        sm.whi[c * WS_STRIDE + kp] = hi;
        sm.wlo[c * WS_STRIDE + kp] = lo;
    }
}

__device__ __forceinline__ void proj_mma_core(ProjSmem& sm, int r0, int warp_n,
                                              int grp, int tg, float acc[8][4]) {
    #pragma unroll
    for (int nt = 0; nt < 8; nt++)
        #pragma unroll
        for (int i = 0; i < 4; i++) acc[nt][i] = 0.f;

    #pragma unroll 1
    for (int kc = 0; kc < 8; kc++) {
        const float* x0 = sm.xs + (r0 + grp) * XS_STRIDE + kc * 16 + tg * 2;
        const float* x1 = x0 + 8 * XS_STRIDE;
        float2 f0 = *(const float2*)x0;
        float2 f1 = *(const float2*)x1;
        float2 f2 = *(const float2*)(x0 + 8);
        float2 f3 = *(const float2*)(x1 + 8);
        uint32_t AH[4], AL[4];
        AH[0] = bfsplit(f0.x, f0.y, AL[0]);
        AH[1] = bfsplit(f1.x, f1.y, AL[1]);
        AH[2] = bfsplit(f2.x, f2.y, AL[2]);
        AH[3] = bfsplit(f3.x, f3.y, AL[3]);
        #pragma unroll
        for (int nt = 0; nt < 8; nt++) {
            int cb = (warp_n * 64 + nt * 8 + grp) * WS_STRIDE + kc * 8 + tg;
            uint32_t bh[2] = { sm.whi[cb], sm.whi[cb + 4] };
            uint32_t bl[2] = { sm.wlo[cb], sm.wlo[cb + 4] };
            mma_bf16(acc[nt], AH, bh);
            mma_bf16(acc[nt], AL, bh);
            mma_bf16(acc[nt], AH, bl);
        }
    }
}

__global__ __launch_bounds__(256) void proj_qkv_kernel(
    const float* __restrict__ x,
    const float* __restrict__ Wq, const float* __restrict__ bq,
    const float* __restrict__ Wk, const float* __restrict__ bk,
    const float* __restrict__ Wv, const float* __restrict__ bv,
    const int* __restrict__ shift_p)
{
    extern __shared__ char smraw[];
    ProjSmem sm = proj_smem(smraw);
    const int t = threadIdx.x;
    const int wid = t >> 5, lane = t & 31, grp = lane >> 2, tg = lane & 3;
    const int warp_m = wid & 3, warp_n = wid >> 2;
    const int s = *shift_p;
    const long R0 = (long)blockIdx.x * 64;

    #pragma unroll
    for (int it = 0; it < 8; it++) {
        int e = t + it * 256;
        int r = e >> 5, c4 = e & 31;
        long R = R0 + r;
        int b  = (int)(R >> 14);
        int r1 = (int)(R >> 7) & 127;
        int r2 = (int)R & 127;
        int hh = (r1 + s) & 127;
        int ww = (r2 + s) & 127;
        ((float4*)(sm.xs + r * XS_STRIDE))[c4] =
            ((const float4*)x)[(((long)b * 128 + hh) * 128 + ww) * 32 + c4];
    }

    const int r0 = warp_m * 16;
    #pragma unroll 1
    for (int pass = 0; pass < 3; pass++) {
        const float* W  = pass == 0 ? Wq : (pass == 1 ? Wk : Wv);
        const float* bb = pass == 0 ? bq : (pass == 1 ? bk : bv);
        float* gOut     = pass == 0 ? g_Q : (pass == 1 ? g_K : g_V);
        __syncthreads();
        stage_W(sm, W, t);
        __syncthreads();

        float acc[8][4];
        proj_mma_core(sm, r0, warp_n, grp, tg, acc);

        float* out0 = gOut + (R0 + r0 + grp) * 128;
        float* out1 = out0 + 8 * 128;
        #pragma unroll
        for (int nt = 0; nt < 8; nt++) {
            int c = warp_n * 64 + nt * 8 + tg * 2;
            float2 bias2 = *(const float2*)(bb + c);
            float2 v0 = { acc[nt][0] + bias2.x, acc[nt][1] + bias2.y };
            float2 v1 = { acc[nt][2] + bias2.x, acc[nt][3] + bias2.y };
            *(float2*)(out0 + c) = v0;
            *(float2*)(out1 + c) = v1;
        }
    }
}

__global__ __launch_bounds__(256) void out_proj_kernel(
    const float* __restrict__ Wp, const float* __restrict__ bp,
    const int* __restrict__ shift_p, float* __restrict__ out)
{
    extern __shared__ char smraw[];
    ProjSmem sm = proj_smem(smraw);
    const int t = threadIdx.x;
    const int wid = t >> 5, lane = t & 31, grp = lane >> 2, tg = lane & 3;
    const int warp_m = wid & 3, warp_n = wid >> 2;
    const int s = *shift_p;
    const long R0 = (long)blockIdx.x * 64;

    #pragma unroll
    for (int it = 0; it < 8; it++) {
        int e = t + it * 256;
        int r = e >> 5, c4 = e & 31;
        ((float4*)(sm.xs + r * XS_STRIDE))[c4] = ((const float4*)g_AO)[R0 * 32 + e];
    }
    stage_W(sm, Wp, t);
    __syncthreads();

    const int r0 = warp_m * 16;
    float acc[8][4];
    proj_mma_core(sm, r0, warp_n, grp, tg, acc);

    long R_0 = R0 + r0 + grp;
    long R_1 = R_0 + 8;
    int b0 = (int)(R_0 >> 14), r10 = (int)(R_0 >> 7) & 127, r20 = (int)R_0 & 127;
    int b1 = (int)(R_1 >> 14), r11 = (int)(R_1 >> 7) & 127, r21 = (int)R_1 & 127;
    float* drow0 = out + (((long)b0 * 128 + ((r10 + s) & 127)) * 128 + ((r20 + s) & 127)) * 128;
    float* drow1 = out + (((long)b1 * 128 + ((r11 + s) & 127)) * 128 + ((r21 + s) & 127)) * 128;
    #pragma unroll
    for (int nt = 0; nt < 8; nt++) {
        int c = warp_n * 64 + nt * 8 + tg * 2;
        float2 bias2 = *(const float2*)(bp + c);
        float2 v0 = { acc[nt][0] + bias2.x, acc[nt][1] + bias2.y };
        float2 v1 = { acc[nt][2] + bias2.x, acc[nt][3] + bias2.y };
        *(float2*)(drow0 + c) = v0;
        *(float2*)(drow1 + c) = v1;
    }
}

// ---------------------------------------------------------------------------
// attention v3: CTA = (window, head, q-half). 256 threads, warp owns 16 query
// rows -> halved register state -> __launch_bounds__(256,3) = 24 warps/SM.
// Single-buffered K/V tiles (36.8 KB static smem), split-bf16 mma.sync,
// fixed-max softmax, flat bias mapping ((q>>5)+31)*47 + (q&31) + 23.
// ---------------------------------------------------------------------------
#define KST 36
__device__ __forceinline__ int bidx(int rowbase, int k) {
    int ix = rowbase - (k >> 5) * 47 - (k & 31);
    return ix < 0 ? ix + BT_N : ix;
}

__global__ __launch_bounds__(256, 3) void attn_kernel(const float* __restrict__ bias_table)
{
    __shared__ float bias_s[BT_N + 3];
    __shared__ uint32_t Khi_s[64 * KST], Klo_s[64 * KST];     // [key][dimpair<=15]
    __shared__ uint32_t Vthi_s[32 * KST], Vtlo_s[32 * KST];   // [dim][keypair<=31]
    __shared__ int rhs_s[32], rws_s[32];

    const int t    = threadIdx.x;
    const int wid  = t >> 5;
    const int lane = t & 31;
    const int g    = lane >> 2;
    const int tg   = lane & 3;
    const int w    = blockIdx.x;
    const int h    = blockIdx.y;
    const int qblk = blockIdx.z;
    const int b  = w >> 6, wi = (w >> 3) & 7, wj = w & 7;
    const float LOG2E = 1.4426950408889634f;

    if (t < 32)       rhs_s[t]      = reflect_idx(wi * 16 + t - 8, 128);
    else if (t < 64)  rws_s[t - 32] = reflect_idx(wj * 16 + (t - 32) - 8, 128);
    for (int i = t; i < BT_N; i += 256) bias_s[i] = bias_table[i * NH + h] * LOG2E;

    // this warp's two 8-row groups: queries q0 (rows g) and q0+8 (rows g+8)
    const int q0 = qblk * 128 + wid * 16 + g;
    const int q1 = q0 + 8;

    // ---- Q fragments: [kc][4] hi/lo ----
    uint32_t QH[2][4], QL[2][4];
    {
        const float qs = 0.17677669529663687f * LOG2E;
        const float* qp0 = g_Q + (((long)b * 128 + wi * 16 + (q0 >> 4)) * 128 + wj * 16 + (q0 & 15)) * 128 + h * 32;
        const float* qp1 = g_Q + (((long)b * 128 + wi * 16 + (q1 >> 4)) * 128 + wj * 16 + (q1 & 15)) * 128 + h * 32;
        #pragma unroll
        for (int kc = 0; kc < 2; kc++) {
            int d0 = kc * 16 + tg * 2;
            float2 f;
            f = *(const float2*)(qp0 + d0);
            QH[kc][0] = bfsplit(f.x * qs, f.y * qs, QL[kc][0]);
            f = *(const float2*)(qp1 + d0);
            QH[kc][1] = bfsplit(f.x * qs, f.y * qs, QL[kc][1]);
            f = *(const float2*)(qp0 + d0 + 8);
            QH[kc][2] = bfsplit(f.x * qs, f.y * qs, QL[kc][2]);
            f = *(const float2*)(qp1 + d0 + 8);
            QH[kc][3] = bfsplit(f.x * qs, f.y * qs, QL[kc][3]);
        }
    }
    // flat bias mapping
    const int qbase0 = ((q0 >> 5) + 31) * 47 + (q0 & 31) + 23;

    float Of[4][4];
    #pragma unroll
    for (int nd = 0; nd < 4; nd++)
        #pragma unroll
        for (int i = 0; i < 4; i++) Of[nd][i] = 0.f;
    float ls[2] = {0.f, 0.f};

    #pragma unroll 1
    for (int tile = 0; tile < 16; tile++) {
        __syncthreads();
        // ---- stage K: 64 keys x 32 dims, hi/lo ----
        #pragma unroll
        for (int it = 0; it < 2; it++) {
            int e   = t + it * 256;
            int key = e >> 3, d4 = e & 7;
            int u = tile * 2 + (key >> 5), v = key & 31;
            long krow = ((long)b * 128 + rhs_s[u]) * 128 + rws_s[v];
            float4 kv = *(const float4*)(g_K + krow * 128 + h * 32 + d4 * 4);
            uint32_t l01, l23;
            uint32_t h01 = bfsplit(kv.x, kv.y, l01);
            uint32_t h23 = bfsplit(kv.z, kv.w, l23);
            Khi_s[key * KST + d4 * 2]     = h01;
            Khi_s[key * KST + d4 * 2 + 1] = h23;
            Klo_s[key * KST + d4 * 2]     = l01;
            Klo_s[key * KST + d4 * 2 + 1] = l23;
        }
        // ---- stage V^T: [dim][keypair] hi/lo ----
        {
            int kp = t >> 3, d4 = t & 7;
            int k0 = 2 * kp, k1 = 2 * kp + 1;
            int u0 = tile * 2 + (k0 >> 5), v0 = k0 & 31;
            int u1 = tile * 2 + (k1 >> 5), v1 = k1 & 31;
            long row0 = ((long)b * 128 + rhs_s[u0]) * 128 + rws_s[v0];
            long row1 = ((long)b * 128 + rhs_s[u1]) * 128 + rws_s[v1];
            float4 a4 = *(const float4*)(g_V + row0 * 128 + h * 32 + d4 * 4);
            float4 c4 = *(const float4*)(g_V + row1 * 128 + h * 32 + d4 * 4);
            const float* av = (const float*)&a4;
            const float* cv = (const float*)&c4;
            #pragma unroll
            for (int i = 0; i < 4; i++) {
                int d = d4 * 4 + i;
                uint32_t lo;
                Vthi_s[d * KST + kp] = bfsplit(av[i], cv[i], lo);
                Vtlo_s[d * KST + kp] = lo;
            }
        }
        __syncthreads();

        #pragma unroll 1
        for (int nb = 0; nb < 4; nb++) {
            uint32_t KHf[2][2][2], KLf[2][2][2];
            #pragma unroll
            for (int j2 = 0; j2 < 2; j2++) {
                int key = (2 * nb + j2) * 8 + g;
                #pragma unroll
                for (int kc = 0; kc < 2; kc++) {
                    KHf[j2][kc][0] = Khi_s[key * KST + kc * 8 + tg];
                    KHf[j2][kc][1] = Khi_s[key * KST + kc * 8 + 4 + tg];
                    KLf[j2][kc][0] = Klo_s[key * KST + kc * 8 + tg];
                    KLf[j2][kc][1] = Klo_s[key * KST + kc * 8 + 4 + tg];
                }
            }
            uint32_t VHf[4][2], VLf[4][2];
            #pragma unroll
            for (int nd = 0; nd < 4; nd++) {
                int d = nd * 8 + g;
                VHf[nd][0] = Vthi_s[d * KST + nb * 8 + tg];
                VHf[nd][1] = Vthi_s[d * KST + nb * 8 + 4 + tg];
                VLf[nd][0] = Vtlo_s[d * KST + nb * 8 + tg];
                VLf[nd][1] = Vtlo_s[d * KST + nb * 8 + 4 + tg];
            }
            float S0[4] = {0.f, 0.f, 0.f, 0.f};
            float S1[4] = {0.f, 0.f, 0.f, 0.f};
            #pragma unroll
            for (int kc = 0; kc < 2; kc++) {
                mma_bf16(S0, QH[kc], KHf[0][kc]);
                mma_bf16(S0, QL[kc], KHf[0][kc]);
                mma_bf16(S0, QH[kc], KLf[0][kc]);
                mma_bf16(S1, QH[kc], KHf[1][kc]);
                mma_bf16(S1, QL[kc], KHf[1][kc]);
                mma_bf16(S1, QH[kc], KLf[1][kc]);
            }
            int kg0 = tile * 64 + nb * 16 + tg * 2;
            int kg8 = kg0 + 8;
            int rb0 = qbase0;
            int rb8 = qbase0 + 8;
            float p0 = ex2f(S0[0] + bias_s[bidx(rb0, kg0)]);
            float p1 = ex2f(S0[1] + bias_s[bidx(rb0, kg0 + 1)]);
            float p2 = ex2f(S0[2] + bias_s[bidx(rb8, kg0)]);
            float p3 = ex2f(S0[3] + bias_s[bidx(rb8, kg0 + 1)]);
            float p4 = ex2f(S1[0] + bias_s[bidx(rb0, kg8)]);
            float p5 = ex2f(S1[1] + bias_s[bidx(rb0, kg8 + 1)]);
            float p6 = ex2f(S1[2] + bias_s[bidx(rb8, kg8)]);
            float p7 = ex2f(S1[3] + bias_s[bidx(rb8, kg8 + 1)]);
            ls[0] += (p0 + p1) + (p4 + p5);
            ls[1] += (p2 + p3) + (p6 + p7);
            uint32_t PH[4], PL[4];
            PH[0] = bfsplit(p0, p1, PL[0]);
            PH[1] = bfsplit(p2, p3, PL[1]);
            PH[2] = bfsplit(p4, p5, PL[2]);
            PH[3] = bfsplit(p6, p7, PL[3]);
            #pragma unroll
            for (int nd = 0; nd < 4; nd++) {
                mma_bf16(Of[nd], PH, VHf[nd]);
                mma_bf16(Of[nd], PL, VHf[nd]);
                mma_bf16(Of[nd], PH, VLf[nd]);
            }
        }
    }

    // ---- finalize: l reduce within quad, scale, store ----
    #pragma unroll
    for (int i = 0; i < 2; i++) {
        ls[i] += __shfl_xor_sync(0xffffffffu, ls[i], 1);
        ls[i] += __shfl_xor_sync(0xffffffffu, ls[i], 2);
        ls[i] = 1.f / ls[i];
    }
    {
        float* o0 = g_AO + (((long)b * 128 + wi * 16 + (q0 >> 4)) * 128 + wj * 16 + (q0 & 15)) * 128 + h * 32;
        float* o1 = g_AO + (((long)b * 128 + wi * 16 + (q1 >> 4)) * 128 + wj * 16 + (q1 & 15)) * 128 + h * 32;
        #pragma unroll
        for (int nd = 0; nd < 4; nd++) {
            float2 v;
            v.x = Of[nd][0] * ls[0]; v.y = Of[nd][1] * ls[0];
            *(float2*)(o0 + nd * 8 + tg * 2) = v;
            v.x = Of[nd][2] * ls[1]; v.y = Of[nd][3] * ls[1];
            *(float2*)(o1 + nd * 8 + tg * 2) = v;
        }
    }
}

// ---------------------------------------------------------------------------
extern "C" void kernel_launch(void* const* d_in, const int* in_sizes, int n_in,
                              void* d_out, int out_size)
{
    const float* x  = (const float*)d_in[0];
    const float* Wq = (const float*)d_in[1];
    const float* bq = (const float*)d_in[2];
    const float* Wk = (const float*)d_in[3];
    const float* bk = (const float*)d_in[4];
    const float* Wv = (const float*)d_in[5];
    const float* bv = (const float*)d_in[6];
    const float* Wp = (const float*)d_in[7];
    const float* bp = (const float*)d_in[8];
    const float* bt = (const float*)d_in[9];
    const int* shift = (const int*)d_in[10];
    float* out = (float*)d_out;

    cudaFuncSetAttribute(proj_qkv_kernel, cudaFuncAttributeMaxDynamicSharedMemorySize, PROJ_SMEM);
    cudaFuncSetAttribute(out_proj_kernel, cudaFuncAttributeMaxDynamicSharedMemorySize, PROJ_SMEM);

    proj_qkv_kernel<<<512, 256, PROJ_SMEM>>>(x, Wq, bq, Wk, bk, Wv, bv, shift);
    attn_kernel    <<<dim3(128, 4, 2), 256>>>(bt);
    out_proj_kernel<<<512, 256, PROJ_SMEM>>>(Wp, bp, shift, out);
}

// round 14
// speedup vs baseline: 1.1015x; 1.1015x over previous
#include <cuda_runtime.h>
#include <cuda_bf16.h>
#include <cstdint>

#define NH 4
#define DIMC 128
#define BT_N 2209   // 47^2
#define EBN  1852   // extended bias table: idx_ext = idx + 8, idx in [-8, 1840]

// Per-pixel layouts (rolled space): 32768 rows x 128.
__device__ __align__(16) float g_Q [32768 * DIMC];
__device__ __align__(16) float g_K [32768 * DIMC];
__device__ __align__(16) float g_V [32768 * DIMC];
__device__ __align__(16) float g_AO[32768 * DIMC];

__device__ __forceinline__ float ex2f(float x) {
    float r; asm("ex2.approx.f32 %0,%1;" : "=f"(r) : "f"(x)); return r;
}
__device__ __forceinline__ int reflect_idx(int p, int n) {
    if (p < 0) p = -p;
    else if (p >= n) p = 2 * n - 2 - p;
    return p;
}
// Split (a,b) into packed bf16 hi (returned; a in low half) and packed lo remainder.
__device__ __forceinline__ uint32_t bfsplit(float a, float b, uint32_t& lo) {
    uint32_t hi;
    asm("cvt.rn.bf16x2.f32 %0,%1,%2;" : "=r"(hi) : "f"(b), "f"(a));
    float ra = __uint_as_float(hi << 16);
    float rb = __uint_as_float(hi & 0xffff0000u);
    asm("cvt.rn.bf16x2.f32 %0,%1,%2;" : "=r"(lo) : "f"(b - rb), "f"(a - ra));
    return hi;
}

// mma.sync m16n8k16 bf16: D(f32x4) += A(4xb32) * B(2xb32)   (sm_80+, non-'a')
__device__ __forceinline__ void mma_bf16(float d[4], const uint32_t a[4], const uint32_t b[2]) {
    asm volatile(
        "mma.sync.aligned.m16n8k16.row.col.f32.bf16.bf16.f32 "
        "{%0,%1,%2,%3},{%4,%5,%6,%7},{%8,%9},{%0,%1,%2,%3};"
        : "+f"(d[0]), "+f"(d[1]), "+f"(d[2]), "+f"(d[3])
        : "r"(a[0]), "r"(a[1]), "r"(a[2]), "r"(a[3]), "r"(b[0]), "r"(b[1]));
}

// ---------------------------------------------------------------------------
// Split-bf16 MMA projection GEMM with PRE-SPLIT X in smem:
// xhi/xlo staged once (bf16x2), inner loop = pure LDS.32 + mma.
// C[64x128] = X[64x128] . W^T + b ; 8 warps (4 m x 2 n).
// ---------------------------------------------------------------------------
#define XP_STRIDE 68
#define WS_STRIDE 68
#define PROJ_SMEM ((2 * 64 * XP_STRIDE + 2 * 128 * WS_STRIDE) * 4)   // 104448

struct ProjSmem {
    uint32_t* xhi;
    uint32_t* xlo;
    uint32_t* whi;
    uint32_t* wlo;
};
__device__ __forceinline__ ProjSmem proj_smem(char* smraw) {
    ProjSmem p;
    p.xhi = (uint32_t*)smraw;
    p.xlo = p.xhi + 64 * XP_STRIDE;
    p.whi = p.xlo + 64 * XP_STRIDE;
    p.wlo = p.whi + 128 * WS_STRIDE;
    return p;
}

__device__ __forceinline__ void stage_W(ProjSmem& sm, const float* __restrict__ W, int t) {
    #pragma unroll
    for (int it = 0; it < 32; it++) {
        int e  = t + it * 256;
        int c  = e >> 6;
        int kp = e & 63;
        float2 wv = ((const float2*)W)[c * 64 + kp];
        uint32_t lo, hi = bfsplit(wv.x, wv.y, lo);
        sm.whi[c * WS_STRIDE + kp] = hi;
        sm.wlo[c * WS_STRIDE + kp] = lo;
    }
}

// store one float4 (dimpairs 2*c4, 2*c4+1) of row r, pre-split
__device__ __forceinline__ void stage_x_elem(ProjSmem& sm, int r, int c4, float4 f) {
    uint32_t lo0, hi0 = bfsplit(f.x, f.y, lo0);
    uint32_t lo1, hi1 = bfsplit(f.z, f.w, lo1);
    sm.xhi[r * XP_STRIDE + 2 * c4]     = hi0;
    sm.xhi[r * XP_STRIDE + 2 * c4 + 1] = hi1;
    sm.xlo[r * XP_STRIDE + 2 * c4]     = lo0;
    sm.xlo[r * XP_STRIDE + 2 * c4 + 1] = lo1;
}

__device__ __forceinline__ void proj_mma_core(ProjSmem& sm, int r0, int warp_n,
                                              int grp, int tg, float acc[8][4]) {
    #pragma unroll
    for (int nt = 0; nt < 8; nt++)
        #pragma unroll
        for (int i = 0; i < 4; i++) acc[nt][i] = 0.f;

    #pragma unroll 1
    for (int kc = 0; kc < 8; kc++) {
        int xb = (r0 + grp) * XP_STRIDE + kc * 8 + tg;
        uint32_t AH[4], AL[4];
        AH[0] = sm.xhi[xb];
        AH[1] = sm.xhi[xb + 8 * XP_STRIDE];
        AH[2] = sm.xhi[xb + 4];
        AH[3] = sm.xhi[xb + 8 * XP_STRIDE + 4];
        AL[0] = sm.xlo[xb];
        AL[1] = sm.xlo[xb + 8 * XP_STRIDE];
        AL[2] = sm.xlo[xb + 4];
        AL[3] = sm.xlo[xb + 8 * XP_STRIDE + 4];
        #pragma unroll
        for (int nt = 0; nt < 8; nt++) {
            int cb = (warp_n * 64 + nt * 8 + grp) * WS_STRIDE + kc * 8 + tg;
            uint32_t bh[2] = { sm.whi[cb], sm.whi[cb + 4] };
            uint32_t bl[2] = { sm.wlo[cb], sm.wlo[cb + 4] };
            mma_bf16(acc[nt], AH, bh);
            mma_bf16(acc[nt], AL, bh);
            mma_bf16(acc[nt], AH, bl);
        }
    }
}

__global__ __launch_bounds__(256) void proj_qkv_kernel(
    const float* __restrict__ x,
    const float* __restrict__ Wq, const float* __restrict__ bq,
    const float* __restrict__ Wk, const float* __restrict__ bk,
    const float* __restrict__ Wv, const float* __restrict__ bv,
    const int* __restrict__ shift_p)
{
    extern __shared__ char smraw[];
    ProjSmem sm = proj_smem(smraw);
    const int t = threadIdx.x;
    const int wid = t >> 5, lane = t & 31, grp = lane >> 2, tg = lane & 3;
    const int warp_m = wid & 3, warp_n = wid >> 2;
    const int s = *shift_p;
    const long R0 = (long)blockIdx.x * 64;

    // gather 64 pixel rows (rolled space), pre-split into xhi/xlo
    #pragma unroll
    for (int it = 0; it < 8; it++) {
        int e = t + it * 256;
        int r = e >> 5, c4 = e & 31;
        long R = R0 + r;
        int b  = (int)(R >> 14);
        int r1 = (int)(R >> 7) & 127;
        int r2 = (int)R & 127;
        int hh = (r1 + s) & 127;
        int ww = (r2 + s) & 127;
        float4 f = ((const float4*)x)[(((long)b * 128 + hh) * 128 + ww) * 32 + c4];
        stage_x_elem(sm, r, c4, f);
    }

    const int r0 = warp_m * 16;
    #pragma unroll 1
    for (int pass = 0; pass < 3; pass++) {
        const float* W  = pass == 0 ? Wq : (pass == 1 ? Wk : Wv);
        const float* bb = pass == 0 ? bq : (pass == 1 ? bk : bv);
        float* gOut     = pass == 0 ? g_Q : (pass == 1 ? g_K : g_V);
        __syncthreads();          // x ready / prior W reads done
        stage_W(sm, W, t);
        __syncthreads();

        float acc[8][4];
        proj_mma_core(sm, r0, warp_n, grp, tg, acc);

        float* out0 = gOut + (R0 + r0 + grp) * 128;
        float* out1 = out0 + 8 * 128;
        #pragma unroll
        for (int nt = 0; nt < 8; nt++) {
            int c = warp_n * 64 + nt * 8 + tg * 2;
            float2 bias2 = *(const float2*)(bb + c);
            float2 v0 = { acc[nt][0] + bias2.x, acc[nt][1] + bias2.y };
            float2 v1 = { acc[nt][2] + bias2.x, acc[nt][3] + bias2.y };
            *(float2*)(out0 + c) = v0;
            *(float2*)(out1 + c) = v1;
        }
    }
}

__global__ __launch_bounds__(256) void out_proj_kernel(
    const float* __restrict__ Wp, const float* __restrict__ bp,
    const int* __restrict__ shift_p, float* __restrict__ out)
{
    extern __shared__ char smraw[];
    ProjSmem sm = proj_smem(smraw);
    const int t = threadIdx.x;
    const int wid = t >> 5, lane = t & 31, grp = lane >> 2, tg = lane & 3;
    const int warp_m = wid & 3, warp_n = wid >> 2;
    const int s = *shift_p;
    const long R0 = (long)blockIdx.x * 64;

    #pragma unroll
    for (int it = 0; it < 8; it++) {
        int e = t + it * 256;
        int r = e >> 5, c4 = e & 31;
        float4 f = ((const float4*)g_AO)[R0 * 32 + e];
        stage_x_elem(sm, r, c4, f);
    }
    stage_W(sm, Wp, t);
    __syncthreads();

    const int r0 = warp_m * 16;
    float acc[8][4];
    proj_mma_core(sm, r0, warp_n, grp, tg, acc);

    long R_0 = R0 + r0 + grp;
    long R_1 = R_0 + 8;
    int b0 = (int)(R_0 >> 14), r10 = (int)(R_0 >> 7) & 127, r20 = (int)R_0 & 127;
    int b1 = (int)(R_1 >> 14), r11 = (int)(R_1 >> 7) & 127, r21 = (int)R_1 & 127;
    float* drow0 = out + (((long)b0 * 128 + ((r10 + s) & 127)) * 128 + ((r20 + s) & 127)) * 128;
    float* drow1 = out + (((long)b1 * 128 + ((r11 + s) & 127)) * 128 + ((r21 + s) & 127)) * 128;
    #pragma unroll
    for (int nt = 0; nt < 8; nt++) {
        int c = warp_n * 64 + nt * 8 + tg * 2;
        float2 bias2 = *(const float2*)(bp + c);
        float2 v0 = { acc[nt][0] + bias2.x, acc[nt][1] + bias2.y };
        float2 v1 = { acc[nt][2] + bias2.x, acc[nt][3] + bias2.y };
        *(float2*)(drow0 + c) = v0;
        *(float2*)(drow1 + c) = v1;
    }
}

// ---------------------------------------------------------------------------
// attention (round-12 winner structure): CTA = (window, head), 256 thr,
// warp owns 32 q-rows (mb=2), double-buffered K/V with register prefetch.
// NEW: extended wrap-free bias table (idx+8), immediate-offset bias loads
// (6 LDS/score-group, shared B0/Bm1), per-tile hoisted bias base.
// ---------------------------------------------------------------------------
#define KST 36
// smem: ebias 1852f (7408B) | KhiB 2*64*36 u32 | KloB | VthiB 2*32*36 | VtloB | rhs 32i | rws 32i
#define ATTN_SMEM (7408 + 18432 + 18432 + 9216 + 9216 + 128 + 128)   // 62960

__global__ __launch_bounds__(256, 2) void attn_kernel(const float* __restrict__ bias_table)
{
    extern __shared__ __align__(16) char smb[];
    float*    ebias_s = (float*)smb;
    uint32_t* KhiB   = (uint32_t*)(smb + 7408);
    uint32_t* KloB   = KhiB + 2 * 64 * KST;
    uint32_t* VthiB  = KloB + 2 * 64 * KST;
    uint32_t* VtloB  = VthiB + 2 * 32 * KST;
    int*      rhs_s  = (int*)(VtloB + 2 * 32 * KST);
    int*      rws_s  = rhs_s + 32;

    const int t    = threadIdx.x;
    const int wid  = t >> 5;
    const int lane = t & 31;
    const int g    = lane >> 2;
    const int tg   = lane & 3;
    const int w = blockIdx.x;
    const int h = blockIdx.y;
    const int b  = w >> 6, wi = (w >> 3) & 7, wj = w & 7;
    const float LOG2E = 1.4426950408889634f;

    if (t < 32)       rhs_s[t]      = reflect_idx(wi * 16 + t - 8, 128);
    else if (t < 64)  rws_s[t - 32] = reflect_idx(wj * 16 + (t - 32) - 8, 128);
    // extended bias table: ebias[j] = bias[wrap(j-8)] * log2e
    for (int i = t; i < EBN; i += 256) {
        int orig = i - 8;
        if (orig < 0) orig += BT_N;
        ebias_s[i] = bias_table[orig * NH + h] * LOG2E;
    }

    // ---- Q fragments: [mb][kc][4] hi/lo ----
    uint32_t QH[2][2][4], QL[2][2][4];
    {
        const float qs = 0.17677669529663687f * LOG2E;
        #pragma unroll
        for (int mb = 0; mb < 2; mb++) {
            int r0 = wid * 32 + mb * 16 + g;
            int ii0 = r0 >> 4,        jj0 = r0 & 15;
            int ii1 = (r0 + 8) >> 4,  jj1 = (r0 + 8) & 15;
            const float* q0 = g_Q + (((long)b * 128 + wi * 16 + ii0) * 128 + wj * 16 + jj0) * 128 + h * 32;
            const float* q1 = g_Q + (((long)b * 128 + wi * 16 + ii1) * 128 + wj * 16 + jj1) * 128 + h * 32;
            #pragma unroll
            for (int kc = 0; kc < 2; kc++) {
                int d0 = kc * 16 + tg * 2;
                float2 f;
                f = *(const float2*)(q0 + d0);
                QH[mb][kc][0] = bfsplit(f.x * qs, f.y * qs, QL[mb][kc][0]);
                f = *(const float2*)(q1 + d0);
                QH[mb][kc][1] = bfsplit(f.x * qs, f.y * qs, QL[mb][kc][1]);
                f = *(const float2*)(q0 + d0 + 8);
                QH[mb][kc][2] = bfsplit(f.x * qs, f.y * qs, QL[mb][kc][2]);
                f = *(const float2*)(q1 + d0 + 8);
                QH[mb][kc][3] = bfsplit(f.x * qs, f.y * qs, QL[mb][kc][3]);
            }
        }
    }
    // ext-bias base per mb: qb = ((q>>5)+31)*47 + (q&31) + 23 + 8, q = wid*32+mb*16+g
    int qb[2];
    qb[0] = (wid + 31) * 47 + 0 * 16 + g + 31;
    qb[1] = (wid + 31) * 47 + 1 * 16 + g + 31;

    float Of[2][4][4];
    #pragma unroll
    for (int mb = 0; mb < 2; mb++)
        #pragma unroll
        for (int nd = 0; nd < 4; nd++)
            #pragma unroll
            for (int i = 0; i < 4; i++) Of[mb][nd][i] = 0.f;
    float ls[4] = {0.f, 0.f, 0.f, 0.f};

    const int kKey0 = t >> 3,        kD4 = t & 7;
    const int kKey1 = (t + 256) >> 3;
    const int vKp   = t >> 3,        vD4 = t & 7;

    __syncthreads();

    // ---- stage tile 0 ----
    {
        #pragma unroll
        for (int it = 0; it < 2; it++) {
            int key = it == 0 ? kKey0 : kKey1;
            int u = (key >> 5), v = key & 31;
            long krow = ((long)b * 128 + rhs_s[u]) * 128 + rws_s[v];
            float4 kv = *(const float4*)(g_K + krow * 128 + h * 32 + kD4 * 4);
            uint32_t l01, l23;
            uint32_t h01 = bfsplit(kv.x, kv.y, l01);
            uint32_t h23 = bfsplit(kv.z, kv.w, l23);
            KhiB[key * KST + kD4 * 2]     = h01;
            KhiB[key * KST + kD4 * 2 + 1] = h23;
            KloB[key * KST + kD4 * 2]     = l01;
            KloB[key * KST + kD4 * 2 + 1] = l23;
        }
        int k0 = 2 * vKp, k1 = 2 * vKp + 1;
        long row0 = ((long)b * 128 + rhs_s[k0 >> 5]) * 128 + rws_s[k0 & 31];
        long row1 = ((long)b * 128 + rhs_s[k1 >> 5]) * 128 + rws_s[k1 & 31];
        float4 a4 = *(const float4*)(g_V + row0 * 128 + h * 32 + vD4 * 4);
        float4 c4 = *(const float4*)(g_V + row1 * 128 + h * 32 + vD4 * 4);
        const float* av = (const float*)&a4;
        const float* cv = (const float*)&c4;
        #pragma unroll
        for (int i = 0; i < 4; i++) {
            int d = vD4 * 4 + i;
            uint32_t lo;
            VthiB[d * KST + vKp] = bfsplit(av[i], cv[i], lo);
            VtloB[d * KST + vKp] = lo;
        }
    }
    __syncthreads();

    #pragma unroll 1
    for (int tile = 0; tile < 16; tile++) {
        const int buf  = tile & 1;
        const int nbuf = buf ^ 1;
        const bool pf  = (tile < 15);

        // ---- prefetch next tile into registers ----
        float4 pkA, pkB, pvA, pvB;
        if (pf) {
            int nt2 = (tile + 1) * 2;
            {
                int u = nt2 + (kKey0 >> 5), v = kKey0 & 31;
                long krow = ((long)b * 128 + rhs_s[u]) * 128 + rws_s[v];
                pkA = *(const float4*)(g_K + krow * 128 + h * 32 + kD4 * 4);
            }
            {
                int u = nt2 + (kKey1 >> 5), v = kKey1 & 31;
                long krow = ((long)b * 128 + rhs_s[u]) * 128 + rws_s[v];
                pkB = *(const float4*)(g_K + krow * 128 + h * 32 + kD4 * 4);
            }
            int k0 = 2 * vKp, k1 = 2 * vKp + 1;
            long row0 = ((long)b * 128 + rhs_s[nt2 + (k0 >> 5)]) * 128 + rws_s[k0 & 31];
            long row1 = ((long)b * 128 + rhs_s[nt2 + (k1 >> 5)]) * 128 + rws_s[k1 & 31];
            pvA = *(const float4*)(g_V + row0 * 128 + h * 32 + vD4 * 4);
            pvB = *(const float4*)(g_V + row1 * 128 + h * 32 + vD4 * 4);
        }

        const uint32_t* Khi_s  = KhiB  + buf * 64 * KST;
        const uint32_t* Klo_s  = KloB  + buf * 64 * KST;
        const uint32_t* Vthi_s = VthiB + buf * 32 * KST;
        const uint32_t* Vtlo_s = VtloB + buf * 32 * KST;

        // per-tile hoisted bias bases (idx_ext = tb - (nb>>1)*47 - (nb&1)*16 - c)
        const int tb0 = qb[0] - tile * 94 - tg * 2;
        const int tb1 = qb[1] - tile * 94 - tg * 2;

        #pragma unroll 1
        for (int nb = 0; nb < 4; nb++) {
            uint32_t KHf[2][2][2], KLf[2][2][2];
            #pragma unroll
            for (int j2 = 0; j2 < 2; j2++) {
                int key = (2 * nb + j2) * 8 + g;
                #pragma unroll
                for (int kc = 0; kc < 2; kc++) {
                    KHf[j2][kc][0] = Khi_s[key * KST + kc * 8 + tg];
                    KHf[j2][kc][1] = Khi_s[key * KST + kc * 8 + 4 + tg];
                    KLf[j2][kc][0] = Klo_s[key * KST + kc * 8 + tg];
                    KLf[j2][kc][1] = Klo_s[key * KST + kc * 8 + 4 + tg];
                }
            }
            uint32_t VHf[4][2], VLf[4][2];
            #pragma unroll
            for (int nd = 0; nd < 4; nd++) {
                int d = nd * 8 + g;
                VHf[nd][0] = Vthi_s[d * KST + nb * 8 + tg];
                VHf[nd][1] = Vthi_s[d * KST + nb * 8 + 4 + tg];
                VLf[nd][0] = Vtlo_s[d * KST + nb * 8 + tg];
                VLf[nd][1] = Vtlo_s[d * KST + nb * 8 + 4 + tg];
            }
            const int nbo = (nb >> 1) * 47 + (nb & 1) * 16;
            #pragma unroll
            for (int mb = 0; mb < 2; mb++) {
                float S0[4] = {0.f, 0.f, 0.f, 0.f};
                float S1[4] = {0.f, 0.f, 0.f, 0.f};
                #pragma unroll
                for (int kc = 0; kc < 2; kc++) {
                    mma_bf16(S0, QH[mb][kc], KHf[0][kc]);
                    mma_bf16(S0, QL[mb][kc], KHf[0][kc]);
                    mma_bf16(S0, QH[mb][kc], KLf[0][kc]);
                    mma_bf16(S1, QH[mb][kc], KHf[1][kc]);
                    mma_bf16(S1, QL[mb][kc], KHf[1][kc]);
                    mma_bf16(S1, QH[mb][kc], KLf[1][kc]);
                }
                // wrap-free bias loads: bb = ext idx of (row g, key kg0)
                const int bb = (mb ? tb1 : tb0) - nbo;
                const float B0  = ebias_s[bb];
                const float Bm1 = ebias_s[bb - 1];
                const float Bp8 = ebias_s[bb + 8];
                const float Bp7 = ebias_s[bb + 7];
                const float Bm8 = ebias_s[bb - 8];
                const float Bm9 = ebias_s[bb - 9];
                float p0 = ex2f(S0[0] + B0);
                float p1 = ex2f(S0[1] + Bm1);
                float p2 = ex2f(S0[2] + Bp8);
                float p3 = ex2f(S0[3] + Bp7);
                float p4 = ex2f(S1[0] + Bm8);
                float p5 = ex2f(S1[1] + Bm9);
                float p6 = ex2f(S1[2] + B0);
                float p7 = ex2f(S1[3] + Bm1);
                ls[mb * 2 + 0] += (p0 + p1) + (p4 + p5);
                ls[mb * 2 + 1] += (p2 + p3) + (p6 + p7);
                uint32_t PH[4], PL[4];
                PH[0] = bfsplit(p0, p1, PL[0]);
                PH[1] = bfsplit(p2, p3, PL[1]);
                PH[2] = bfsplit(p4, p5, PL[2]);
                PH[3] = bfsplit(p6, p7, PL[3]);
                #pragma unroll
                for (int nd = 0; nd < 4; nd++) {
                    mma_bf16(Of[mb][nd], PH, VHf[nd]);
                    mma_bf16(Of[mb][nd], PL, VHf[nd]);
                    mma_bf16(Of[mb][nd], PH, VLf[nd]);
                }
            }
        }

        // ---- write prefetched tile into the other buffer ----
        if (pf) {
            uint32_t* Kh = KhiB  + nbuf * 64 * KST;
            uint32_t* Kl = KloB  + nbuf * 64 * KST;
            uint32_t* Vh = VthiB + nbuf * 32 * KST;
            uint32_t* Vl = VtloB + nbuf * 32 * KST;
            {
                uint32_t l01, l23;
                uint32_t h01 = bfsplit(pkA.x, pkA.y, l01);
                uint32_t h23 = bfsplit(pkA.z, pkA.w, l23);
                Kh[kKey0 * KST + kD4 * 2]     = h01;
                Kh[kKey0 * KST + kD4 * 2 + 1] = h23;
                Kl[kKey0 * KST + kD4 * 2]     = l01;
                Kl[kKey0 * KST + kD4 * 2 + 1] = l23;
                h01 = bfsplit(pkB.x, pkB.y, l01);
                h23 = bfsplit(pkB.z, pkB.w, l23);
                Kh[kKey1 * KST + kD4 * 2]     = h01;
                Kh[kKey1 * KST + kD4 * 2 + 1] = h23;
                Kl[kKey1 * KST + kD4 * 2]     = l01;
                Kl[kKey1 * KST + kD4 * 2 + 1] = l23;
            }
            const float* av = (const float*)&pvA;
            const float* cv = (const float*)&pvB;
            #pragma unroll
            for (int i = 0; i < 4; i++) {
                int d = vD4 * 4 + i;
                uint32_t lo;
                Vh[d * KST + vKp] = bfsplit(av[i], cv[i], lo);
                Vl[d * KST + vKp] = lo;
            }
        }
        __syncthreads();
    }

    // ---- finalize ----
    #pragma unroll
    for (int i = 0; i < 4; i++) {
        ls[i] += __shfl_xor_sync(0xffffffffu, ls[i], 1);
        ls[i] += __shfl_xor_sync(0xffffffffu, ls[i], 2);
        ls[i] = 1.f / ls[i];
    }
    #pragma unroll
    for (int mb = 0; mb < 2; mb++) {
        int r0 = wid * 32 + mb * 16 + g;
        int ii0 = r0 >> 4,        jj0 = r0 & 15;
        int ii1 = (r0 + 8) >> 4,  jj1 = (r0 + 8) & 15;
        float* o0 = g_AO + (((long)b * 128 + wi * 16 + ii0) * 128 + wj * 16 + jj0) * 128 + h * 32;
        float* o1 = g_AO + (((long)b * 128 + wi * 16 + ii1) * 128 + wj * 16 + jj1) * 128 + h * 32;
        float invlo = ls[mb * 2 + 0];
        float invhi = ls[mb * 2 + 1];
        #pragma unroll
        for (int nd = 0; nd < 4; nd++) {
            float2 v;
            v.x = Of[mb][nd][0] * invlo; v.y = Of[mb][nd][1] * invlo;
            *(float2*)(o0 + nd * 8 + tg * 2) = v;
            v.x = Of[mb][nd][2] * invhi; v.y = Of[mb][nd][3] * invhi;
            *(float2*)(o1 + nd * 8 + tg * 2) = v;
        }
    }
}

// ---------------------------------------------------------------------------
extern "C" void kernel_launch(void* const* d_in, const int* in_sizes, int n_in,
                              void* d_out, int out_size)
{
    const float* x  = (const float*)d_in[0];
    const float* Wq = (const float*)d_in[1];
    const float* bq = (const float*)d_in[2];
    const float* Wk = (const float*)d_in[3];
    const float* bk = (const float*)d_in[4];
    const float* Wv = (const float*)d_in[5];
    const float* bv = (const float*)d_in[6];
    const float* Wp = (const float*)d_in[7];
    const float* bp = (const float*)d_in[8];
    const float* bt = (const float*)d_in[9];
    const int* shift = (const int*)d_in[10];
    float* out = (float*)d_out;

    cudaFuncSetAttribute(proj_qkv_kernel, cudaFuncAttributeMaxDynamicSharedMemorySize, PROJ_SMEM);
    cudaFuncSetAttribute(out_proj_kernel, cudaFuncAttributeMaxDynamicSharedMemorySize, PROJ_SMEM);
    cudaFuncSetAttribute(attn_kernel,     cudaFuncAttributeMaxDynamicSharedMemorySize, ATTN_SMEM);

    proj_qkv_kernel<<<512, 256, PROJ_SMEM>>>(x, Wq, bq, Wk, bk, Wv, bv, shift);
    attn_kernel    <<<dim3(128, 4), 256, ATTN_SMEM>>>(bt);
    out_proj_kernel<<<512, 256, PROJ_SMEM>>>(Wp, bp, shift, out);
}

// round 15
// speedup vs baseline: 1.7266x; 1.5675x over previous
#include <cuda_runtime.h>
#include <cuda_bf16.h>
#include <cstdint>

#define NH 4
#define DIMC 128
#define BT_N 2209   // 47^2
#define EBN  1852   // extended bias table: idx_ext = idx + 8, idx in [-8, 1840]

// Per-pixel layouts (rolled space): 32768 rows x 128.
__device__ __align__(16) float g_Q [32768 * DIMC];
__device__ __align__(16) float g_K [32768 * DIMC];
__device__ __align__(16) float g_V [32768 * DIMC];
__device__ __align__(16) float g_AO[32768 * DIMC];

__device__ __forceinline__ float ex2f(float x) {
    float r; asm("ex2.approx.f32 %0,%1;" : "=f"(r) : "f"(x)); return r;
}
__device__ __forceinline__ int reflect_idx(int p, int n) {
    if (p < 0) p = -p;
    else if (p >= n) p = 2 * n - 2 - p;
    return p;
}
// Split (a,b) into packed bf16 hi (returned; a in low half) and packed lo remainder.
__device__ __forceinline__ uint32_t bfsplit(float a, float b, uint32_t& lo) {
    uint32_t hi;
    asm("cvt.rn.bf16x2.f32 %0,%1,%2;" : "=r"(hi) : "f"(b), "f"(a));
    float ra = __uint_as_float(hi << 16);
    float rb = __uint_as_float(hi & 0xffff0000u);
    asm("cvt.rn.bf16x2.f32 %0,%1,%2;" : "=r"(lo) : "f"(b - rb), "f"(a - ra));
    return hi;
}
// Pack (a,b) to f16x2 (a in low half).
__device__ __forceinline__ uint32_t f16pack(float a, float b) {
    uint32_t r;
    asm("cvt.rn.f16x2.f32 %0,%1,%2;" : "=r"(r) : "f"(b), "f"(a));
    return r;
}

// mma.sync m16n8k16 bf16: D(f32x4) += A(4xb32) * B(2xb32)
__device__ __forceinline__ void mma_bf16(float d[4], const uint32_t a[4], const uint32_t b[2]) {
    asm volatile(
        "mma.sync.aligned.m16n8k16.row.col.f32.bf16.bf16.f32 "
        "{%0,%1,%2,%3},{%4,%5,%6,%7},{%8,%9},{%0,%1,%2,%3};"
        : "+f"(d[0]), "+f"(d[1]), "+f"(d[2]), "+f"(d[3])
        : "r"(a[0]), "r"(a[1]), "r"(a[2]), "r"(a[3]), "r"(b[0]), "r"(b[1]));
}
// mma.sync m16n8k16 fp16: D(f32x4) += A(4xb32) * B(2xb32)
__device__ __forceinline__ void mma_f16v(float d[4], const uint32_t a[4], const uint32_t b[2]) {
    asm volatile(
        "mma.sync.aligned.m16n8k16.row.col.f32.f16.f16.f32 "
        "{%0,%1,%2,%3},{%4,%5,%6,%7},{%8,%9},{%0,%1,%2,%3};"
        : "+f"(d[0]), "+f"(d[1]), "+f"(d[2]), "+f"(d[3])
        : "r"(a[0]), "r"(a[1]), "r"(a[2]), "r"(a[3]), "r"(b[0]), "r"(b[1]));
}

// ---------------------------------------------------------------------------
// Split-bf16 MMA projection GEMM with pre-split X (passing, unchanged).
// ---------------------------------------------------------------------------
#define XP_STRIDE 68
#define WS_STRIDE 68
#define PROJ_SMEM ((2 * 64 * XP_STRIDE + 2 * 128 * WS_STRIDE) * 4)   // 104448

struct ProjSmem {
    uint32_t* xhi;
    uint32_t* xlo;
    uint32_t* whi;
    uint32_t* wlo;
};
__device__ __forceinline__ ProjSmem proj_smem(char* smraw) {
    ProjSmem p;
    p.xhi = (uint32_t*)smraw;
    p.xlo = p.xhi + 64 * XP_STRIDE;
    p.whi = p.xlo + 64 * XP_STRIDE;
    p.wlo = p.whi + 128 * WS_STRIDE;
    return p;
}

__device__ __forceinline__ void stage_W(ProjSmem& sm, const float* __restrict__ W, int t) {
    #pragma unroll
    for (int it = 0; it < 32; it++) {
        int e  = t + it * 256;
        int c  = e >> 6;
        int kp = e & 63;
        float2 wv = ((const float2*)W)[c * 64 + kp];
        uint32_t lo, hi = bfsplit(wv.x, wv.y, lo);
        sm.whi[c * WS_STRIDE + kp] = hi;
        sm.wlo[c * WS_STRIDE + kp] = lo;
    }
}

__device__ __forceinline__ void stage_x_elem(ProjSmem& sm, int r, int c4, float4 f) {
    uint32_t lo0, hi0 = bfsplit(f.x, f.y, lo0);
    uint32_t lo1, hi1 = bfsplit(f.z, f.w, lo1);
    sm.xhi[r * XP_STRIDE + 2 * c4]     = hi0;
    sm.xhi[r * XP_STRIDE + 2 * c4 + 1] = hi1;
    sm.xlo[r * XP_STRIDE + 2 * c4]     = lo0;
    sm.xlo[r * XP_STRIDE + 2 * c4 + 1] = lo1;
}

__device__ __forceinline__ void proj_mma_core(ProjSmem& sm, int r0, int warp_n,
                                              int grp, int tg, float acc[8][4]) {
    #pragma unroll
    for (int nt = 0; nt < 8; nt++)
        #pragma unroll
        for (int i = 0; i < 4; i++) acc[nt][i] = 0.f;

    #pragma unroll 1
    for (int kc = 0; kc < 8; kc++) {
        int xb = (r0 + grp) * XP_STRIDE + kc * 8 + tg;
        uint32_t AH[4], AL[4];
        AH[0] = sm.xhi[xb];
        AH[1] = sm.xhi[xb + 8 * XP_STRIDE];
        AH[2] = sm.xhi[xb + 4];
        AH[3] = sm.xhi[xb + 8 * XP_STRIDE + 4];
        AL[0] = sm.xlo[xb];
        AL[1] = sm.xlo[xb + 8 * XP_STRIDE];
        AL[2] = sm.xlo[xb + 4];
        AL[3] = sm.xlo[xb + 8 * XP_STRIDE + 4];
        #pragma unroll
        for (int nt = 0; nt < 8; nt++) {
            int cb = (warp_n * 64 + nt * 8 + grp) * WS_STRIDE + kc * 8 + tg;
            uint32_t bh[2] = { sm.whi[cb], sm.whi[cb + 4] };
            uint32_t bl[2] = { sm.wlo[cb], sm.wlo[cb + 4] };
            mma_bf16(acc[nt], AH, bh);
            mma_bf16(acc[nt], AL, bh);
            mma_bf16(acc[nt], AH, bl);
        }
    }
}

__global__ __launch_bounds__(256) void proj_qkv_kernel(
    const float* __restrict__ x,
    const float* __restrict__ Wq, const float* __restrict__ bq,
    const float* __restrict__ Wk, const float* __restrict__ bk,
    const float* __restrict__ Wv, const float* __restrict__ bv,
    const int* __restrict__ shift_p)
{
    extern __shared__ char smraw[];
    ProjSmem sm = proj_smem(smraw);
    const int t = threadIdx.x;
    const int wid = t >> 5, lane = t & 31, grp = lane >> 2, tg = lane & 3;
    const int warp_m = wid & 3, warp_n = wid >> 2;
    const int s = *shift_p;
    const long R0 = (long)blockIdx.x * 64;

    #pragma unroll
    for (int it = 0; it < 8; it++) {
        int e = t + it * 256;
        int r = e >> 5, c4 = e & 31;
        long R = R0 + r;
        int b  = (int)(R >> 14);
        int r1 = (int)(R >> 7) & 127;
        int r2 = (int)R & 127;
        int hh = (r1 + s) & 127;
        int ww = (r2 + s) & 127;
        float4 f = ((const float4*)x)[(((long)b * 128 + hh) * 128 + ww) * 32 + c4];
        stage_x_elem(sm, r, c4, f);
    }

    const int r0 = warp_m * 16;
    #pragma unroll 1
    for (int pass = 0; pass < 3; pass++) {
        const float* W  = pass == 0 ? Wq : (pass == 1 ? Wk : Wv);
        const float* bb = pass == 0 ? bq : (pass == 1 ? bk : bv);
        float* gOut     = pass == 0 ? g_Q : (pass == 1 ? g_K : g_V);
        __syncthreads();
        stage_W(sm, W, t);
        __syncthreads();

        float acc[8][4];
        proj_mma_core(sm, r0, warp_n, grp, tg, acc);

        float* out0 = gOut + (R0 + r0 + grp) * 128;
        float* out1 = out0 + 8 * 128;
        #pragma unroll
        for (int nt = 0; nt < 8; nt++) {
            int c = warp_n * 64 + nt * 8 + tg * 2;
            float2 bias2 = *(const float2*)(bb + c);
            float2 v0 = { acc[nt][0] + bias2.x, acc[nt][1] + bias2.y };
            float2 v1 = { acc[nt][2] + bias2.x, acc[nt][3] + bias2.y };
            *(float2*)(out0 + c) = v0;
            *(float2*)(out1 + c) = v1;
        }
    }
}

__global__ __launch_bounds__(256) void out_proj_kernel(
    const float* __restrict__ Wp, const float* __restrict__ bp,
    const int* __restrict__ shift_p, float* __restrict__ out)
{
    extern __shared__ char smraw[];
    ProjSmem sm = proj_smem(smraw);
    const int t = threadIdx.x;
    const int wid = t >> 5, lane = t & 31, grp = lane >> 2, tg = lane & 3;
    const int warp_m = wid & 3, warp_n = wid >> 2;
    const int s = *shift_p;
    const long R0 = (long)blockIdx.x * 64;

    #pragma unroll
    for (int it = 0; it < 8; it++) {
        int e = t + it * 256;
        int r = e >> 5, c4 = e & 31;
        float4 f = ((const float4*)g_AO)[R0 * 32 + e];
        stage_x_elem(sm, r, c4, f);
    }
    stage_W(sm, Wp, t);
    __syncthreads();

    const int r0 = warp_m * 16;
    float acc[8][4];
    proj_mma_core(sm, r0, warp_n, grp, tg, acc);

    long R_0 = R0 + r0 + grp;
    long R_1 = R_0 + 8;
    int b0 = (int)(R_0 >> 14), r10 = (int)(R_0 >> 7) & 127, r20 = (int)R_0 & 127;
    int b1 = (int)(R_1 >> 14), r11 = (int)(R_1 >> 7) & 127, r21 = (int)R_1 & 127;
    float* drow0 = out + (((long)b0 * 128 + ((r10 + s) & 127)) * 128 + ((r20 + s) & 127)) * 128;
    float* drow1 = out + (((long)b1 * 128 + ((r11 + s) & 127)) * 128 + ((r21 + s) & 127)) * 128;
    #pragma unroll
    for (int nt = 0; nt < 8; nt++) {
        int c = warp_n * 64 + nt * 8 + tg * 2;
        float2 bias2 = *(const float2*)(bp + c);
        float2 v0 = { acc[nt][0] + bias2.x, acc[nt][1] + bias2.y };
        float2 v1 = { acc[nt][2] + bias2.x, acc[nt][3] + bias2.y };
        *(float2*)(drow0 + c) = v0;
        *(float2*)(drow1 + c) = v1;
    }
}

// ---------------------------------------------------------------------------
// attention: fp16 single-term mma (3x fewer HMMA than split-bf16 — was
// tensor-throughput-bound). CTA = (window, head), 256 thr, warp owns 32 q-rows,
// double-buffered K/V with register prefetch, extended wrap-free bias table.
// fp16 rounding (2^-11) error budget ~1e-4 final (10x under 1e-3 gate).
// ---------------------------------------------------------------------------
#define KST 36
// smem: ebias 1852f (7408B) | KhB 2*64*36 u32 (18432B) | VhB 2*32*36 (9216B) | rhs 128 | rws 128
#define ATTN_SMEM (7408 + 18432 + 9216 + 128 + 128)   // 35312

__global__ __launch_bounds__(256, 2) void attn_kernel(const float* __restrict__ bias_table)
{
    extern __shared__ __align__(16) char smb[];
    float*    ebias_s = (float*)smb;
    uint32_t* KhB    = (uint32_t*)(smb + 7408);
    uint32_t* VhB    = KhB + 2 * 64 * KST;
    int*      rhs_s  = (int*)(VhB + 2 * 32 * KST);
    int*      rws_s  = rhs_s + 32;

    const int t    = threadIdx.x;
    const int wid  = t >> 5;
    const int lane = t & 31;
    const int g    = lane >> 2;
    const int tg   = lane & 3;
    const int w = blockIdx.x;
    const int h = blockIdx.y;
    const int b  = w >> 6, wi = (w >> 3) & 7, wj = w & 7;
    const float LOG2E = 1.4426950408889634f;

    if (t < 32)       rhs_s[t]      = reflect_idx(wi * 16 + t - 8, 128);
    else if (t < 64)  rws_s[t - 32] = reflect_idx(wj * 16 + (t - 32) - 8, 128);
    for (int i = t; i < EBN; i += 256) {
        int orig = i - 8;
        if (orig < 0) orig += BT_N;
        ebias_s[i] = bias_table[orig * NH + h] * LOG2E;
    }

    // ---- Q fragments (fp16): [mb][kc][4] ----
    uint32_t QH[2][2][4];
    {
        const float qs = 0.17677669529663687f * LOG2E;
        #pragma unroll
        for (int mb = 0; mb < 2; mb++) {
            int r0 = wid * 32 + mb * 16 + g;
            int ii0 = r0 >> 4,        jj0 = r0 & 15;
            int ii1 = (r0 + 8) >> 4,  jj1 = (r0 + 8) & 15;
            const float* q0 = g_Q + (((long)b * 128 + wi * 16 + ii0) * 128 + wj * 16 + jj0) * 128 + h * 32;
            const float* q1 = g_Q + (((long)b * 128 + wi * 16 + ii1) * 128 + wj * 16 + jj1) * 128 + h * 32;
            #pragma unroll
            for (int kc = 0; kc < 2; kc++) {
                int d0 = kc * 16 + tg * 2;
                float2 f;
                f = *(const float2*)(q0 + d0);
                QH[mb][kc][0] = f16pack(f.x * qs, f.y * qs);
                f = *(const float2*)(q1 + d0);
                QH[mb][kc][1] = f16pack(f.x * qs, f.y * qs);
                f = *(const float2*)(q0 + d0 + 8);
                QH[mb][kc][2] = f16pack(f.x * qs, f.y * qs);
                f = *(const float2*)(q1 + d0 + 8);
                QH[mb][kc][3] = f16pack(f.x * qs, f.y * qs);
            }
        }
    }
    // ext-bias base per mb
    int qb[2];
    qb[0] = (wid + 31) * 47 + 0 * 16 + g + 31;
    qb[1] = (wid + 31) * 47 + 1 * 16 + g + 31;

    float Of[2][4][4];
    #pragma unroll
    for (int mb = 0; mb < 2; mb++)
        #pragma unroll
        for (int nd = 0; nd < 4; nd++)
            #pragma unroll
            for (int i = 0; i < 4; i++) Of[mb][nd][i] = 0.f;
    float ls[4] = {0.f, 0.f, 0.f, 0.f};

    const int kKey0 = t >> 3,        kD4 = t & 7;
    const int kKey1 = (t + 256) >> 3;
    const int vKp   = t >> 3,        vD4 = t & 7;

    __syncthreads();

    // ---- stage tile 0 (fp16) ----
    {
        #pragma unroll
        for (int it = 0; it < 2; it++) {
            int key = it == 0 ? kKey0 : kKey1;
            int u = (key >> 5), v = key & 31;
            long krow = ((long)b * 128 + rhs_s[u]) * 128 + rws_s[v];
            float4 kv = *(const float4*)(g_K + krow * 128 + h * 32 + kD4 * 4);
            KhB[key * KST + kD4 * 2]     = f16pack(kv.x, kv.y);
            KhB[key * KST + kD4 * 2 + 1] = f16pack(kv.z, kv.w);
        }
        int k0 = 2 * vKp, k1 = 2 * vKp + 1;
        long row0 = ((long)b * 128 + rhs_s[k0 >> 5]) * 128 + rws_s[k0 & 31];
        long row1 = ((long)b * 128 + rhs_s[k1 >> 5]) * 128 + rws_s[k1 & 31];
        float4 a4 = *(const float4*)(g_V + row0 * 128 + h * 32 + vD4 * 4);
        float4 c4 = *(const float4*)(g_V + row1 * 128 + h * 32 + vD4 * 4);
        const float* av = (const float*)&a4;
        const float* cv = (const float*)&c4;
        #pragma unroll
        for (int i = 0; i < 4; i++) {
            int d = vD4 * 4 + i;
            VhB[d * KST + vKp] = f16pack(av[i], cv[i]);
        }
    }
    __syncthreads();

    #pragma unroll 1
    for (int tile = 0; tile < 16; tile++) {
        const int buf  = tile & 1;
        const int nbuf = buf ^ 1;
        const bool pf  = (tile < 15);

        // ---- prefetch next tile into registers ----
        float4 pkA, pkB, pvA, pvB;
        if (pf) {
            int nt2 = (tile + 1) * 2;
            {
                int u = nt2 + (kKey0 >> 5), v = kKey0 & 31;
                long krow = ((long)b * 128 + rhs_s[u]) * 128 + rws_s[v];
                pkA = *(const float4*)(g_K + krow * 128 + h * 32 + kD4 * 4);
            }
            {
                int u = nt2 + (kKey1 >> 5), v = kKey1 & 31;
                long krow = ((long)b * 128 + rhs_s[u]) * 128 + rws_s[v];
                pkB = *(const float4*)(g_K + krow * 128 + h * 32 + kD4 * 4);
            }
            int k0 = 2 * vKp, k1 = 2 * vKp + 1;
            long row0 = ((long)b * 128 + rhs_s[nt2 + (k0 >> 5)]) * 128 + rws_s[k0 & 31];
            long row1 = ((long)b * 128 + rhs_s[nt2 + (k1 >> 5)]) * 128 + rws_s[k1 & 31];
            pvA = *(const float4*)(g_V + row0 * 128 + h * 32 + vD4 * 4);
            pvB = *(const float4*)(g_V + row1 * 128 + h * 32 + vD4 * 4);
        }

        const uint32_t* Kh_s = KhB + buf * 64 * KST;
        const uint32_t* Vh_s = VhB + buf * 32 * KST;

        const int tb0 = qb[0] - tile * 94 - tg * 2;
        const int tb1 = qb[1] - tile * 94 - tg * 2;

        #pragma unroll 1
        for (int nb = 0; nb < 4; nb++) {
            uint32_t KHf[2][2][2];
            #pragma unroll
            for (int j2 = 0; j2 < 2; j2++) {
                int key = (2 * nb + j2) * 8 + g;
                #pragma unroll
                for (int kc = 0; kc < 2; kc++) {
                    KHf[j2][kc][0] = Kh_s[key * KST + kc * 8 + tg];
                    KHf[j2][kc][1] = Kh_s[key * KST + kc * 8 + 4 + tg];
                }
            }
            uint32_t VHf[4][2];
            #pragma unroll
            for (int nd = 0; nd < 4; nd++) {
                int d = nd * 8 + g;
                VHf[nd][0] = Vh_s[d * KST + nb * 8 + tg];
                VHf[nd][1] = Vh_s[d * KST + nb * 8 + 4 + tg];
            }
            const int nbo = (nb >> 1) * 47 + (nb & 1) * 16;
            #pragma unroll
            for (int mb = 0; mb < 2; mb++) {
                float S0[4] = {0.f, 0.f, 0.f, 0.f};
                float S1[4] = {0.f, 0.f, 0.f, 0.f};
                #pragma unroll
                for (int kc = 0; kc < 2; kc++) {
                    mma_f16v(S0, QH[mb][kc], KHf[0][kc]);
                    mma_f16v(S1, QH[mb][kc], KHf[1][kc]);
                }
                const int bb = (mb ? tb1 : tb0) - nbo;
                const float B0  = ebias_s[bb];
                const float Bm1 = ebias_s[bb - 1];
                const float Bp8 = ebias_s[bb + 8];
                const float Bp7 = ebias_s[bb + 7];
                const float Bm8 = ebias_s[bb - 8];
                const float Bm9 = ebias_s[bb - 9];
                float p0 = ex2f(S0[0] + B0);
                float p1 = ex2f(S0[1] + Bm1);
                float p2 = ex2f(S0[2] + Bp8);
                float p3 = ex2f(S0[3] + Bp7);
                float p4 = ex2f(S1[0] + Bm8);
                float p5 = ex2f(S1[1] + Bm9);
                float p6 = ex2f(S1[2] + B0);
                float p7 = ex2f(S1[3] + Bm1);
                ls[mb * 2 + 0] += (p0 + p1) + (p4 + p5);
                ls[mb * 2 + 1] += (p2 + p3) + (p6 + p7);
                uint32_t PH[4];
                PH[0] = f16pack(p0, p1);
                PH[1] = f16pack(p2, p3);
                PH[2] = f16pack(p4, p5);
                PH[3] = f16pack(p6, p7);
                #pragma unroll
                for (int nd = 0; nd < 4; nd++)
                    mma_f16v(Of[mb][nd], PH, VHf[nd]);
            }
        }

        // ---- write prefetched tile into the other buffer ----
        if (pf) {
            uint32_t* Kh = KhB + nbuf * 64 * KST;
            uint32_t* Vh = VhB + nbuf * 32 * KST;
            Kh[kKey0 * KST + kD4 * 2]     = f16pack(pkA.x, pkA.y);
            Kh[kKey0 * KST + kD4 * 2 + 1] = f16pack(pkA.z, pkA.w);
            Kh[kKey1 * KST + kD4 * 2]     = f16pack(pkB.x, pkB.y);
            Kh[kKey1 * KST + kD4 * 2 + 1] = f16pack(pkB.z, pkB.w);
            const float* av = (const float*)&pvA;
            const float* cv = (const float*)&pvB;
            #pragma unroll
            for (int i = 0; i < 4; i++) {
                int d = vD4 * 4 + i;
                Vh[d * KST + vKp] = f16pack(av[i], cv[i]);
            }
        }
        __syncthreads();
    }

    // ---- finalize ----
    #pragma unroll
    for (int i = 0; i < 4; i++) {
        ls[i] += __shfl_xor_sync(0xffffffffu, ls[i], 1);
        ls[i] += __shfl_xor_sync(0xffffffffu, ls[i], 2);
        ls[i] = 1.f / ls[i];
    }
    #pragma unroll
    for (int mb = 0; mb < 2; mb++) {
        int r0 = wid * 32 + mb * 16 + g;
        int ii0 = r0 >> 4,        jj0 = r0 & 15;
        int ii1 = (r0 + 8) >> 4,  jj1 = (r0 + 8) & 15;
        float* o0 = g_AO + (((long)b * 128 + wi * 16 + ii0) * 128 + wj * 16 + jj0) * 128 + h * 32;
        float* o1 = g_AO + (((long)b * 128 + wi * 16 + ii1) * 128 + wj * 16 + jj1) * 128 + h * 32;
        float invlo = ls[mb * 2 + 0];
        float invhi = ls[mb * 2 + 1];
        #pragma unroll
        for (int nd = 0; nd < 4; nd++) {
            float2 v;
            v.x = Of[mb][nd][0] * invlo; v.y = Of[mb][nd][1] * invlo;
            *(float2*)(o0 + nd * 8 + tg * 2) = v;
            v.x = Of[mb][nd][2] * invhi; v.y = Of[mb][nd][3] * invhi;
            *(float2*)(o1 + nd * 8 + tg * 2) = v;
        }
    }
}

// ---------------------------------------------------------------------------
extern "C" void kernel_launch(void* const* d_in, const int* in_sizes, int n_in,
                              void* d_out, int out_size)
{
    const float* x  = (const float*)d_in[0];
    const float* Wq = (const float*)d_in[1];
    const float* bq = (const float*)d_in[2];
    const float* Wk = (const float*)d_in[3];
    const float* bk = (const float*)d_in[4];
    const float* Wv = (const float*)d_in[5];
    const float* bv = (const float*)d_in[6];
    const float* Wp = (const float*)d_in[7];
    const float* bp = (const float*)d_in[8];
    const float* bt = (const float*)d_in[9];
    const int* shift = (const int*)d_in[10];
    float* out = (float*)d_out;

    cudaFuncSetAttribute(proj_qkv_kernel, cudaFuncAttributeMaxDynamicSharedMemorySize, PROJ_SMEM);
    cudaFuncSetAttribute(out_proj_kernel, cudaFuncAttributeMaxDynamicSharedMemorySize, PROJ_SMEM);
    cudaFuncSetAttribute(attn_kernel,     cudaFuncAttributeMaxDynamicSharedMemorySize, ATTN_SMEM);

    proj_qkv_kernel<<<512, 256, PROJ_SMEM>>>(x, Wq, bq, Wk, bk, Wv, bv, shift);
    attn_kernel    <<<dim3(128, 4), 256, ATTN_SMEM>>>(bt);
    out_proj_kernel<<<512, 256, PROJ_SMEM>>>(Wp, bp, shift, out);
}

// round 16
// speedup vs baseline: 2.0252x; 1.1730x over previous
#include <cuda_runtime.h>
#include <cuda_bf16.h>
#include <cstdint>

#define NH 4
#define DIMC 128
#define BT_N 2209   // 47^2
#define EBN  1852   // extended bias table: idx_ext = idx + 8, idx in [-8, 1840]

// Per-pixel layouts (rolled space): 32768 rows x 128.
__device__ __align__(16) float g_Q [32768 * DIMC];
__device__ __align__(16) float g_K [32768 * DIMC];
__device__ __align__(16) float g_V [32768 * DIMC];
__device__ __align__(16) float g_AO[32768 * DIMC];

__device__ __forceinline__ float ex2f(float x) {
    float r; asm("ex2.approx.f32 %0,%1;" : "=f"(r) : "f"(x)); return r;
}
__device__ __forceinline__ int reflect_idx(int p, int n) {
    if (p < 0) p = -p;
    else if (p >= n) p = 2 * n - 2 - p;
    return p;
}
// Pack (a,b) to f16x2 (a in low half).
__device__ __forceinline__ uint32_t f16pack(float a, float b) {
    uint32_t r;
    asm("cvt.rn.f16x2.f32 %0,%1,%2;" : "=r"(r) : "f"(b), "f"(a));
    return r;
}

// mma.sync m16n8k16 fp16: D(f32x4) += A(4xb32) * B(2xb32)
__device__ __forceinline__ void mma_f16v(float d[4], const uint32_t a[4], const uint32_t b[2]) {
    asm volatile(
        "mma.sync.aligned.m16n8k16.row.col.f32.f16.f16.f32 "
        "{%0,%1,%2,%3},{%4,%5,%6,%7},{%8,%9},{%0,%1,%2,%3};"
        : "+f"(d[0]), "+f"(d[1]), "+f"(d[2]), "+f"(d[3])
        : "r"(a[0]), "r"(a[1]), "r"(a[2]), "r"(a[3]), "r"(b[0]), "r"(b[1]));
}

// ---------------------------------------------------------------------------
// fp16 MMA projection GEMM: C[64x128] = X[64x128] . W^T + b
// Paired-u64 smem layout: elem[row][pair] = (frag kp, frag kp+4) where
// pair = (kp>>3)*4 + (kp&3). Stride 36 u64 (72 u32) -> conflict-free LDS.64
// (banks grp*8 + tg*2, distinct within each 16-lane phase).
// 8 warps (4 m-tiles x 2 n-halves), 1 mma per (kc, nt).
// ---------------------------------------------------------------------------
#define P_ST32 72                                      // u32 stride per row
#define PROJ_SMEM ((64 * P_ST32 + 128 * P_ST32) * 4)   // 55296

struct ProjSmem {
    uint32_t* xp;   // [64][72] u32
    uint32_t* wp;   // [128][72] u32
};
__device__ __forceinline__ ProjSmem proj_smem(char* smraw) {
    ProjSmem p;
    p.xp = (uint32_t*)smraw;
    p.wp = p.xp + 64 * P_ST32;
    return p;
}
__device__ __forceinline__ int pair_idx(int kp) {   // u32 index within a row
    return ((kp >> 3) * 4 + (kp & 3)) * 2 + ((kp >> 2) & 1);
}

__device__ __forceinline__ void stage_W(ProjSmem& sm, const float* __restrict__ W, int t) {
    #pragma unroll
    for (int it = 0; it < 32; it++) {
        int e  = t + it * 256;
        int c  = e >> 6;           // 0..127
        int kp = e & 63;           // 0..63
        float2 wv = ((const float2*)W)[c * 64 + kp];
        sm.wp[c * P_ST32 + pair_idx(kp)] = f16pack(wv.x, wv.y);
    }
}

// stage one float4 of row r (f16x2 elements kp=2*c4, 2*c4+1)
__device__ __forceinline__ void stage_x_elem(ProjSmem& sm, int r, int c4, float4 f) {
    sm.xp[r * P_ST32 + pair_idx(2 * c4)]     = f16pack(f.x, f.y);
    sm.xp[r * P_ST32 + pair_idx(2 * c4 + 1)] = f16pack(f.z, f.w);
}

__device__ __forceinline__ void proj_mma_core(ProjSmem& sm, int r0, int warp_n,
                                              int grp, int tg, float acc[8][4]) {
    #pragma unroll
    for (int nt = 0; nt < 8; nt++)
        #pragma unroll
        for (int i = 0; i < 4; i++) acc[nt][i] = 0.f;

    #pragma unroll 1
    for (int kc = 0; kc < 8; kc++) {
        const int pe = (kc * 4 + tg) * 2;   // u32 offset of this pair
        uint2 a0 = *(const uint2*)(sm.xp + (r0 + grp) * P_ST32 + pe);
        uint2 a1 = *(const uint2*)(sm.xp + (r0 + grp + 8) * P_ST32 + pe);
        uint32_t AH[4] = { a0.x, a1.x, a0.y, a1.y };
        #pragma unroll
        for (int nt = 0; nt < 8; nt++) {
            uint2 bv = *(const uint2*)(sm.wp + (warp_n * 64 + nt * 8 + grp) * P_ST32 + pe);
            uint32_t bh[2] = { bv.x, bv.y };
            mma_f16v(acc[nt], AH, bh);
        }
    }
}

__global__ __launch_bounds__(256) void proj_qkv_kernel(
    const float* __restrict__ x,
    const float* __restrict__ Wq, const float* __restrict__ bq,
    const float* __restrict__ Wk, const float* __restrict__ bk,
    const float* __restrict__ Wv, const float* __restrict__ bv,
    const int* __restrict__ shift_p)
{
    extern __shared__ char smraw[];
    ProjSmem sm = proj_smem(smraw);
    const int t = threadIdx.x;
    const int wid = t >> 5, lane = t & 31, grp = lane >> 2, tg = lane & 3;
    const int warp_m = wid & 3, warp_n = wid >> 2;
    const int s = *shift_p;
    const long R0 = (long)blockIdx.x * 64;

    // gather 64 pixel rows (rolled space), pack fp16 into paired layout
    #pragma unroll
    for (int it = 0; it < 8; it++) {
        int e = t + it * 256;
        int r = e >> 5, c4 = e & 31;
        long R = R0 + r;
        int b  = (int)(R >> 14);
        int r1 = (int)(R >> 7) & 127;
        int r2 = (int)R & 127;
        int hh = (r1 + s) & 127;
        int ww = (r2 + s) & 127;
        float4 f = ((const float4*)x)[(((long)b * 128 + hh) * 128 + ww) * 32 + c4];
        stage_x_elem(sm, r, c4, f);
    }

    const int r0 = warp_m * 16;
    #pragma unroll 1
    for (int pass = 0; pass < 3; pass++) {
        const float* W  = pass == 0 ? Wq : (pass == 1 ? Wk : Wv);
        const float* bb = pass == 0 ? bq : (pass == 1 ? bk : bv);
        float* gOut     = pass == 0 ? g_Q : (pass == 1 ? g_K : g_V);
        __syncthreads();          // x ready / prior W reads done
        stage_W(sm, W, t);
        __syncthreads();

        float acc[8][4];
        proj_mma_core(sm, r0, warp_n, grp, tg, acc);

        float* out0 = gOut + (R0 + r0 + grp) * 128;
        float* out1 = out0 + 8 * 128;
        #pragma unroll
        for (int nt = 0; nt < 8; nt++) {
            int c = warp_n * 64 + nt * 8 + tg * 2;
            float2 bias2 = *(const float2*)(bb + c);
            float2 v0 = { acc[nt][0] + bias2.x, acc[nt][1] + bias2.y };
            float2 v1 = { acc[nt][2] + bias2.x, acc[nt][3] + bias2.y };
            *(float2*)(out0 + c) = v0;
            *(float2*)(out1 + c) = v1;
        }
    }
}

__global__ __launch_bounds__(256) void out_proj_kernel(
    const float* __restrict__ Wp, const float* __restrict__ bp,
    const int* __restrict__ shift_p, float* __restrict__ out)
{
    extern __shared__ char smraw[];
    ProjSmem sm = proj_smem(smraw);
    const int t = threadIdx.x;
    const int wid = t >> 5, lane = t & 31, grp = lane >> 2, tg = lane & 3;
    const int warp_m = wid & 3, warp_n = wid >> 2;
    const int s = *shift_p;
    const long R0 = (long)blockIdx.x * 64;

    #pragma unroll
    for (int it = 0; it < 8; it++) {
        int e = t + it * 256;
        int r = e >> 5, c4 = e & 31;
        float4 f = ((const float4*)g_AO)[R0 * 32 + e];
        stage_x_elem(sm, r, c4, f);
    }
    stage_W(sm, Wp, t);
    __syncthreads();

    const int r0 = warp_m * 16;
    float acc[8][4];
    proj_mma_core(sm, r0, warp_n, grp, tg, acc);

    long R_0 = R0 + r0 + grp;
    long R_1 = R_0 + 8;
    int b0 = (int)(R_0 >> 14), r10 = (int)(R_0 >> 7) & 127, r20 = (int)R_0 & 127;
    int b1 = (int)(R_1 >> 14), r11 = (int)(R_1 >> 7) & 127, r21 = (int)R_1 & 127;
    float* drow0 = out + (((long)b0 * 128 + ((r10 + s) & 127)) * 128 + ((r20 + s) & 127)) * 128;
    float* drow1 = out + (((long)b1 * 128 + ((r11 + s) & 127)) * 128 + ((r21 + s) & 127)) * 128;
    #pragma unroll
    for (int nt = 0; nt < 8; nt++) {
        int c = warp_n * 64 + nt * 8 + tg * 2;
        float2 bias2 = *(const float2*)(bp + c);
        float2 v0 = { acc[nt][0] + bias2.x, acc[nt][1] + bias2.y };
        float2 v1 = { acc[nt][2] + bias2.x, acc[nt][3] + bias2.y };
        *(float2*)(drow0 + c) = v0;
        *(float2*)(drow1 + c) = v1;
    }
}

// ---------------------------------------------------------------------------
// attention: fp16 single-term mma (round-15 winner, unchanged).
// CTA = (window, head), 256 thr, warp owns 32 q-rows, double-buffered K/V
// with register prefetch, extended wrap-free bias table.
// ---------------------------------------------------------------------------
#define KST 36
#define ATTN_SMEM (7408 + 18432 + 9216 + 128 + 128)   // 35312

__global__ __launch_bounds__(256, 2) void attn_kernel(const float* __restrict__ bias_table)
{
    extern __shared__ __align__(16) char smb[];
    float*    ebias_s = (float*)smb;
    uint32_t* KhB    = (uint32_t*)(smb + 7408);
    uint32_t* VhB    = KhB + 2 * 64 * KST;
    int*      rhs_s  = (int*)(VhB + 2 * 32 * KST);
    int*      rws_s  = rhs_s + 32;

    const int t    = threadIdx.x;
    const int wid  = t >> 5;
    const int lane = t & 31;
    const int g    = lane >> 2;
    const int tg   = lane & 3;
    const int w = blockIdx.x;
    const int h = blockIdx.y;
    const int b  = w >> 6, wi = (w >> 3) & 7, wj = w & 7;
    const float LOG2E = 1.4426950408889634f;

    if (t < 32)       rhs_s[t]      = reflect_idx(wi * 16 + t - 8, 128);
    else if (t < 64)  rws_s[t - 32] = reflect_idx(wj * 16 + (t - 32) - 8, 128);
    for (int i = t; i < EBN; i += 256) {
        int orig = i - 8;
        if (orig < 0) orig += BT_N;
        ebias_s[i] = bias_table[orig * NH + h] * LOG2E;
    }

    // ---- Q fragments (fp16): [mb][kc][4] ----
    uint32_t QH[2][2][4];
    {
        const float qs = 0.17677669529663687f * LOG2E;
        #pragma unroll
        for (int mb = 0; mb < 2; mb++) {
            int r0 = wid * 32 + mb * 16 + g;
            int ii0 = r0 >> 4,        jj0 = r0 & 15;
            int ii1 = (r0 + 8) >> 4,  jj1 = (r0 + 8) & 15;
            const float* q0 = g_Q + (((long)b * 128 + wi * 16 + ii0) * 128 + wj * 16 + jj0) * 128 + h * 32;
            const float* q1 = g_Q + (((long)b * 128 + wi * 16 + ii1) * 128 + wj * 16 + jj1) * 128 + h * 32;
            #pragma unroll
            for (int kc = 0; kc < 2; kc++) {
                int d0 = kc * 16 + tg * 2;
                float2 f;
                f = *(const float2*)(q0 + d0);
                QH[mb][kc][0] = f16pack(f.x * qs, f.y * qs);
                f = *(const float2*)(q1 + d0);
                QH[mb][kc][1] = f16pack(f.x * qs, f.y * qs);
                f = *(const float2*)(q0 + d0 + 8);
                QH[mb][kc][2] = f16pack(f.x * qs, f.y * qs);
                f = *(const float2*)(q1 + d0 + 8);
                QH[mb][kc][3] = f16pack(f.x * qs, f.y * qs);
            }
        }
    }
    int qb[2];
    qb[0] = (wid + 31) * 47 + 0 * 16 + g + 31;
    qb[1] = (wid + 31) * 47 + 1 * 16 + g + 31;

    float Of[2][4][4];
    #pragma unroll
    for (int mb = 0; mb < 2; mb++)
        #pragma unroll
        for (int nd = 0; nd < 4; nd++)
            #pragma unroll
            for (int i = 0; i < 4; i++) Of[mb][nd][i] = 0.f;
    float ls[4] = {0.f, 0.f, 0.f, 0.f};

    const int kKey0 = t >> 3,        kD4 = t & 7;
    const int kKey1 = (t + 256) >> 3;
    const int vKp   = t >> 3,        vD4 = t & 7;

    __syncthreads();

    // ---- stage tile 0 (fp16) ----
    {
        #pragma unroll
        for (int it = 0; it < 2; it++) {
            int key = it == 0 ? kKey0 : kKey1;
            int u = (key >> 5), v = key & 31;
            long krow = ((long)b * 128 + rhs_s[u]) * 128 + rws_s[v];
            float4 kv = *(const float4*)(g_K + krow * 128 + h * 32 + kD4 * 4);
            KhB[key * KST + kD4 * 2]     = f16pack(kv.x, kv.y);
            KhB[key * KST + kD4 * 2 + 1] = f16pack(kv.z, kv.w);
        }
        int k0 = 2 * vKp, k1 = 2 * vKp + 1;
        long row0 = ((long)b * 128 + rhs_s[k0 >> 5]) * 128 + rws_s[k0 & 31];
        long row1 = ((long)b * 128 + rhs_s[k1 >> 5]) * 128 + rws_s[k1 & 31];
        float4 a4 = *(const float4*)(g_V + row0 * 128 + h * 32 + vD4 * 4);
        float4 c4 = *(const float4*)(g_V + row1 * 128 + h * 32 + vD4 * 4);
        const float* av = (const float*)&a4;
        const float* cv = (const float*)&c4;
        #pragma unroll
        for (int i = 0; i < 4; i++) {
            int d = vD4 * 4 + i;
            VhB[d * KST + vKp] = f16pack(av[i], cv[i]);
        }
    }
    __syncthreads();

    #pragma unroll 1
    for (int tile = 0; tile < 16; tile++) {
        const int buf  = tile & 1;
        const int nbuf = buf ^ 1;
        const bool pf  = (tile < 15);

        float4 pkA, pkB, pvA, pvB;
        if (pf) {
            int nt2 = (tile + 1) * 2;
            {
                int u = nt2 + (kKey0 >> 5), v = kKey0 & 31;
                long krow = ((long)b * 128 + rhs_s[u]) * 128 + rws_s[v];
                pkA = *(const float4*)(g_K + krow * 128 + h * 32 + kD4 * 4);
            }
            {
                int u = nt2 + (kKey1 >> 5), v = kKey1 & 31;
                long krow = ((long)b * 128 + rhs_s[u]) * 128 + rws_s[v];
                pkB = *(const float4*)(g_K + krow * 128 + h * 32 + kD4 * 4);
            }
            int k0 = 2 * vKp, k1 = 2 * vKp + 1;
            long row0 = ((long)b * 128 + rhs_s[nt2 + (k0 >> 5)]) * 128 + rws_s[k0 & 31];
            long row1 = ((long)b * 128 + rhs_s[nt2 + (k1 >> 5)]) * 128 + rws_s[k1 & 31];
            pvA = *(const float4*)(g_V + row0 * 128 + h * 32 + vD4 * 4);
            pvB = *(const float4*)(g_V + row1 * 128 + h * 32 + vD4 * 4);
        }

        const uint32_t* Kh_s = KhB + buf * 64 * KST;
        const uint32_t* Vh_s = VhB + buf * 32 * KST;

        const int tb0 = qb[0] - tile * 94 - tg * 2;
        const int tb1 = qb[1] - tile * 94 - tg * 2;

        #pragma unroll 1
        for (int nb = 0; nb < 4; nb++) {
            uint32_t KHf[2][2][2];
            #pragma unroll
            for (int j2 = 0; j2 < 2; j2++) {
                int key = (2 * nb + j2) * 8 + g;
                #pragma unroll
                for (int kc = 0; kc < 2; kc++) {
                    KHf[j2][kc][0] = Kh_s[key * KST + kc * 8 + tg];
                    KHf[j2][kc][1] = Kh_s[key * KST + kc * 8 + 4 + tg];
                }
            }
            uint32_t VHf[4][2];
            #pragma unroll
            for (int nd = 0; nd < 4; nd++) {
                int d = nd * 8 + g;
                VHf[nd][0] = Vh_s[d * KST + nb * 8 + tg];
                VHf[nd][1] = Vh_s[d * KST + nb * 8 + 4 + tg];
            }
            const int nbo = (nb >> 1) * 47 + (nb & 1) * 16;
            #pragma unroll
            for (int mb = 0; mb < 2; mb++) {
                float S0[4] = {0.f, 0.f, 0.f, 0.f};
                float S1[4] = {0.f, 0.f, 0.f, 0.f};
                #pragma unroll
                for (int kc = 0; kc < 2; kc++) {
                    mma_f16v(S0, QH[mb][kc], KHf[0][kc]);
                    mma_f16v(S1, QH[mb][kc], KHf[1][kc]);
                }
                const int bb = (mb ? tb1 : tb0) - nbo;
                const float B0  = ebias_s[bb];
                const float Bm1 = ebias_s[bb - 1];
                const float Bp8 = ebias_s[bb + 8];
                const float Bp7 = ebias_s[bb + 7];
                const float Bm8 = ebias_s[bb - 8];
                const float Bm9 = ebias_s[bb - 9];
                float p0 = ex2f(S0[0] + B0);
                float p1 = ex2f(S0[1] + Bm1);
                float p2 = ex2f(S0[2] + Bp8);
                float p3 = ex2f(S0[3] + Bp7);
                float p4 = ex2f(S1[0] + Bm8);
                float p5 = ex2f(S1[1] + Bm9);
                float p6 = ex2f(S1[2] + B0);
                float p7 = ex2f(S1[3] + Bm1);
                ls[mb * 2 + 0] += (p0 + p1) + (p4 + p5);
                ls[mb * 2 + 1] += (p2 + p3) + (p6 + p7);
                uint32_t PH[4];
                PH[0] = f16pack(p0, p1);
                PH[1] = f16pack(p2, p3);
                PH[2] = f16pack(p4, p5);
                PH[3] = f16pack(p6, p7);
                #pragma unroll
                for (int nd = 0; nd < 4; nd++)
                    mma_f16v(Of[mb][nd], PH, VHf[nd]);
            }
        }

        if (pf) {
            uint32_t* Kh = KhB + nbuf * 64 * KST;
            uint32_t* Vh = VhB + nbuf * 32 * KST;
            Kh[kKey0 * KST + kD4 * 2]     = f16pack(pkA.x, pkA.y);
            Kh[kKey0 * KST + kD4 * 2 + 1] = f16pack(pkA.z, pkA.w);
            Kh[kKey1 * KST + kD4 * 2]     = f16pack(pkB.x, pkB.y);
            Kh[kKey1 * KST + kD4 * 2 + 1] = f16pack(pkB.z, pkB.w);
            const float* av = (const float*)&pvA;
            const float* cv = (const float*)&pvB;
            #pragma unroll
            for (int i = 0; i < 4; i++) {
                int d = vD4 * 4 + i;
                Vh[d * KST + vKp] = f16pack(av[i], cv[i]);
            }
        }
        __syncthreads();
    }

    // ---- finalize ----
    #pragma unroll
    for (int i = 0; i < 4; i++) {
        ls[i] += __shfl_xor_sync(0xffffffffu, ls[i], 1);
        ls[i] += __shfl_xor_sync(0xffffffffu, ls[i], 2);
        ls[i] = 1.f / ls[i];
    }
    #pragma unroll
    for (int mb = 0; mb < 2; mb++) {
        int r0 = wid * 32 + mb * 16 + g;
        int ii0 = r0 >> 4,        jj0 = r0 & 15;
        int ii1 = (r0 + 8) >> 4,  jj1 = (r0 + 8) & 15;
        float* o0 = g_AO + (((long)b * 128 + wi * 16 + ii0) * 128 + wj * 16 + jj0) * 128 + h * 32;
        float* o1 = g_AO + (((long)b * 128 + wi * 16 + ii1) * 128 + wj * 16 + jj1) * 128 + h * 32;
        float invlo = ls[mb * 2 + 0];
        float invhi = ls[mb * 2 + 1];
        #pragma unroll
        for (int nd = 0; nd < 4; nd++) {
            float2 v;
            v.x = Of[mb][nd][0] * invlo; v.y = Of[mb][nd][1] * invlo;
            *(float2*)(o0 + nd * 8 + tg * 2) = v;
            v.x = Of[mb][nd][2] * invhi; v.y = Of[mb][nd][3] * invhi;
            *(float2*)(o1 + nd * 8 + tg * 2) = v;
        }
    }
}

// ---------------------------------------------------------------------------
extern "C" void kernel_launch(void* const* d_in, const int* in_sizes, int n_in,
                              void* d_out, int out_size)
{
    const float* x  = (const float*)d_in[0];
    const float* Wq = (const float*)d_in[1];
    const float* bq = (const float*)d_in[2];
    const float* Wk = (const float*)d_in[3];
    const float* bk = (const float*)d_in[4];
    const float* Wv = (const float*)d_in[5];
    const float* bv = (const float*)d_in[6];
    const float* Wp = (const float*)d_in[7];
    const float* bp = (const float*)d_in[8];
    const float* bt = (const float*)d_in[9];
    const int* shift = (const int*)d_in[10];
    float* out = (float*)d_out;

    cudaFuncSetAttribute(proj_qkv_kernel, cudaFuncAttributeMaxDynamicSharedMemorySize, PROJ_SMEM);
    cudaFuncSetAttribute(out_proj_kernel, cudaFuncAttributeMaxDynamicSharedMemorySize, PROJ_SMEM);
    cudaFuncSetAttribute(attn_kernel,     cudaFuncAttributeMaxDynamicSharedMemorySize, ATTN_SMEM);

    proj_qkv_kernel<<<512, 256, PROJ_SMEM>>>(x, Wq, bq, Wk, bk, Wv, bv, shift);
    attn_kernel    <<<dim3(128, 4), 256, ATTN_SMEM>>>(bt);
    out_proj_kernel<<<512, 256, PROJ_SMEM>>>(Wp, bp, shift, out);
}

// round 17
// speedup vs baseline: 2.1688x; 1.0709x over previous
#include <cuda_runtime.h>
#include <cuda_bf16.h>
#include <cstdint>

#define NH 4
#define DIMC 128
#define BT_N 2209   // 47^2
#define EBN  1852   // extended bias table: idx_ext = idx + 8, idx in [-8, 1840]

// Per-pixel layouts (rolled space): 32768 rows x 128.
__device__ __align__(16) float g_Q [32768 * DIMC];
__device__ __align__(16) float g_K [32768 * DIMC];
__device__ __align__(16) float g_V [32768 * DIMC];
__device__ __align__(16) float g_AO[32768 * DIMC];

__device__ __forceinline__ float ex2f(float x) {
    float r; asm("ex2.approx.f32 %0,%1;" : "=f"(r) : "f"(x)); return r;
}
__device__ __forceinline__ int reflect_idx(int p, int n) {
    if (p < 0) p = -p;
    else if (p >= n) p = 2 * n - 2 - p;
    return p;
}
// Pack (a,b) to f16x2 (a in low half).
__device__ __forceinline__ uint32_t f16pack(float a, float b) {
    uint32_t r;
    asm("cvt.rn.f16x2.f32 %0,%1,%2;" : "=r"(r) : "f"(b), "f"(a));
    return r;
}

// mma.sync m16n8k16 fp16: D(f32x4) += A(4xb32) * B(2xb32)
__device__ __forceinline__ void mma_f16v(float d[4], const uint32_t a[4], const uint32_t b[2]) {
    asm volatile(
        "mma.sync.aligned.m16n8k16.row.col.f32.f16.f16.f32 "
        "{%0,%1,%2,%3},{%4,%5,%6,%7},{%8,%9},{%0,%1,%2,%3};"
        : "+f"(d[0]), "+f"(d[1]), "+f"(d[2]), "+f"(d[3])
        : "r"(a[0]), "r"(a[1]), "r"(a[2]), "r"(a[3]), "r"(b[0]), "r"(b[1]));
}

// ---------------------------------------------------------------------------
// fp16 MMA projection GEMM: C[128x128] = X[128x128] . W^T + b per CTA
// (128 rows/CTA: W staged once feeds two 64-row m-halves -> halved W traffic).
// Paired-u64 smem layout, stride 72 u32, conflict-free LDS.64.
// 8 warps (4 m-tiles x 2 n-halves), warp does m-half 0 then m-half 1.
// ---------------------------------------------------------------------------
#define P_ST32 72                                        // u32 stride per row
#define PROJ_SMEM ((128 * P_ST32 + 128 * P_ST32) * 4)    // 73728

struct ProjSmem {
    uint32_t* xp;   // [128][72] u32
    uint32_t* wp;   // [128][72] u32
};
__device__ __forceinline__ ProjSmem proj_smem(char* smraw) {
    ProjSmem p;
    p.xp = (uint32_t*)smraw;
    p.wp = p.xp + 128 * P_ST32;
    return p;
}
__device__ __forceinline__ int pair_idx(int kp) {   // u32 index within a row
    return ((kp >> 3) * 4 + (kp & 3)) * 2 + ((kp >> 2) & 1);
}

__device__ __forceinline__ void stage_W(ProjSmem& sm, const float* __restrict__ W, int t) {
    #pragma unroll
    for (int it = 0; it < 32; it++) {
        int e  = t + it * 256;
        int c  = e >> 6;           // 0..127
        int kp = e & 63;           // 0..63
        float2 wv = ((const float2*)W)[c * 64 + kp];
        sm.wp[c * P_ST32 + pair_idx(kp)] = f16pack(wv.x, wv.y);
    }
}

__device__ __forceinline__ void stage_x_elem(ProjSmem& sm, int r, int c4, float4 f) {
    sm.xp[r * P_ST32 + pair_idx(2 * c4)]     = f16pack(f.x, f.y);
    sm.xp[r * P_ST32 + pair_idx(2 * c4 + 1)] = f16pack(f.z, f.w);
}

__device__ __forceinline__ void proj_mma_core(ProjSmem& sm, int r0, int warp_n,
                                              int grp, int tg, float acc[8][4]) {
    #pragma unroll
    for (int nt = 0; nt < 8; nt++)
        #pragma unroll
        for (int i = 0; i < 4; i++) acc[nt][i] = 0.f;

    #pragma unroll 1
    for (int kc = 0; kc < 8; kc++) {
        const int pe = (kc * 4 + tg) * 2;   // u32 offset of this pair
        uint2 a0 = *(const uint2*)(sm.xp + (r0 + grp) * P_ST32 + pe);
        uint2 a1 = *(const uint2*)(sm.xp + (r0 + grp + 8) * P_ST32 + pe);
        uint32_t AH[4] = { a0.x, a1.x, a0.y, a1.y };
        #pragma unroll
        for (int nt = 0; nt < 8; nt++) {
            uint2 bv = *(const uint2*)(sm.wp + (warp_n * 64 + nt * 8 + grp) * P_ST32 + pe);
            uint32_t bh[2] = { bv.x, bv.y };
            mma_f16v(acc[nt], AH, bh);
        }
    }
}

__global__ __launch_bounds__(256) void proj_qkv_kernel(
    const float* __restrict__ x,
    const float* __restrict__ Wq, const float* __restrict__ bq,
    const float* __restrict__ Wk, const float* __restrict__ bk,
    const float* __restrict__ Wv, const float* __restrict__ bv,
    const int* __restrict__ shift_p)
{
    extern __shared__ char smraw[];
    ProjSmem sm = proj_smem(smraw);
    const int t = threadIdx.x;
    const int wid = t >> 5, lane = t & 31, grp = lane >> 2, tg = lane & 3;
    const int warp_m = wid & 3, warp_n = wid >> 2;
    const int s = *shift_p;
    const long R0 = (long)blockIdx.x * 128;

    // gather 128 pixel rows (rolled space), pack fp16 into paired layout
    #pragma unroll
    for (int it = 0; it < 16; it++) {
        int e = t + it * 256;
        int r = e >> 5, c4 = e & 31;
        long R = R0 + r;
        int b  = (int)(R >> 14);
        int r1 = (int)(R >> 7) & 127;
        int r2 = (int)R & 127;
        int hh = (r1 + s) & 127;
        int ww = (r2 + s) & 127;
        float4 f = ((const float4*)x)[(((long)b * 128 + hh) * 128 + ww) * 32 + c4];
        stage_x_elem(sm, r, c4, f);
    }

    #pragma unroll 1
    for (int pass = 0; pass < 3; pass++) {
        const float* W  = pass == 0 ? Wq : (pass == 1 ? Wk : Wv);
        const float* bb = pass == 0 ? bq : (pass == 1 ? bk : bv);
        float* gOut     = pass == 0 ? g_Q : (pass == 1 ? g_K : g_V);
        __syncthreads();          // x ready / prior W reads done
        stage_W(sm, W, t);
        __syncthreads();

        #pragma unroll 1
        for (int mh = 0; mh < 2; mh++) {
            const int r0 = mh * 64 + warp_m * 16;
            float acc[8][4];
            proj_mma_core(sm, r0, warp_n, grp, tg, acc);

            float* out0 = gOut + (R0 + r0 + grp) * 128;
            float* out1 = out0 + 8 * 128;
            #pragma unroll
            for (int nt = 0; nt < 8; nt++) {
                int c = warp_n * 64 + nt * 8 + tg * 2;
                float2 bias2 = *(const float2*)(bb + c);
                float2 v0 = { acc[nt][0] + bias2.x, acc[nt][1] + bias2.y };
                float2 v1 = { acc[nt][2] + bias2.x, acc[nt][3] + bias2.y };
                *(float2*)(out0 + c) = v0;
                *(float2*)(out1 + c) = v1;
            }
        }
    }
}

__global__ __launch_bounds__(256) void out_proj_kernel(
    const float* __restrict__ Wp, const float* __restrict__ bp,
    const int* __restrict__ shift_p, float* __restrict__ out)
{
    extern __shared__ char smraw[];
    ProjSmem sm = proj_smem(smraw);
    const int t = threadIdx.x;
    const int wid = t >> 5, lane = t & 31, grp = lane >> 2, tg = lane & 3;
    const int warp_m = wid & 3, warp_n = wid >> 2;
    const int s = *shift_p;
    const long R0 = (long)blockIdx.x * 128;

    #pragma unroll
    for (int it = 0; it < 16; it++) {
        int e = t + it * 256;
        int r = e >> 5, c4 = e & 31;
        float4 f = ((const float4*)g_AO)[R0 * 32 + e];
        stage_x_elem(sm, r, c4, f);
    }
    stage_W(sm, Wp, t);
    __syncthreads();

    #pragma unroll 1
    for (int mh = 0; mh < 2; mh++) {
        const int r0 = mh * 64 + warp_m * 16;
        float acc[8][4];
        proj_mma_core(sm, r0, warp_n, grp, tg, acc);

        long R_0 = R0 + r0 + grp;
        long R_1 = R_0 + 8;
        int b0 = (int)(R_0 >> 14), r10 = (int)(R_0 >> 7) & 127, r20 = (int)R_0 & 127;
        int b1 = (int)(R_1 >> 14), r11 = (int)(R_1 >> 7) & 127, r21 = (int)R_1 & 127;
        float* drow0 = out + (((long)b0 * 128 + ((r10 + s) & 127)) * 128 + ((r20 + s) & 127)) * 128;
        float* drow1 = out + (((long)b1 * 128 + ((r11 + s) & 127)) * 128 + ((r21 + s) & 127)) * 128;
        #pragma unroll
        for (int nt = 0; nt < 8; nt++) {
            int c = warp_n * 64 + nt * 8 + tg * 2;
            float2 bias2 = *(const float2*)(bp + c);
            float2 v0 = { acc[nt][0] + bias2.x, acc[nt][1] + bias2.y };
            float2 v1 = { acc[nt][2] + bias2.x, acc[nt][3] + bias2.y };
            *(float2*)(drow0 + c) = v0;
            *(float2*)(drow1 + c) = v1;
        }
    }
}

// ---------------------------------------------------------------------------
// attention: fp16 single-term mma. CTA = (window, head), 256 thr, warp owns
// 32 q-rows, double-buffered K/V with register prefetch, ext wrap-free bias.
// nb loop unrolled x2 for cross-iteration ILP (was the suspected issue binder).
// ---------------------------------------------------------------------------
#define KST 36
#define ATTN_SMEM (7408 + 18432 + 9216 + 128 + 128)   // 35312

__global__ __launch_bounds__(256, 2) void attn_kernel(const float* __restrict__ bias_table)
{
    extern __shared__ __align__(16) char smb[];
    float*    ebias_s = (float*)smb;
    uint32_t* KhB    = (uint32_t*)(smb + 7408);
    uint32_t* VhB    = KhB + 2 * 64 * KST;
    int*      rhs_s  = (int*)(VhB + 2 * 32 * KST);
    int*      rws_s  = rhs_s + 32;

    const int t    = threadIdx.x;
    const int wid  = t >> 5;
    const int lane = t & 31;
    const int g    = lane >> 2;
    const int tg   = lane & 3;
    const int w = blockIdx.x;
    const int h = blockIdx.y;
    const int b  = w >> 6, wi = (w >> 3) & 7, wj = w & 7;
    const float LOG2E = 1.4426950408889634f;

    if (t < 32)       rhs_s[t]      = reflect_idx(wi * 16 + t - 8, 128);
    else if (t < 64)  rws_s[t - 32] = reflect_idx(wj * 16 + (t - 32) - 8, 128);
    for (int i = t; i < EBN; i += 256) {
        int orig = i - 8;
        if (orig < 0) orig += BT_N;
        ebias_s[i] = bias_table[orig * NH + h] * LOG2E;
    }

    // ---- Q fragments (fp16): [mb][kc][4] ----
    uint32_t QH[2][2][4];
    {
        const float qs = 0.17677669529663687f * LOG2E;
        #pragma unroll
        for (int mb = 0; mb < 2; mb++) {
            int r0 = wid * 32 + mb * 16 + g;
            int ii0 = r0 >> 4,        jj0 = r0 & 15;
            int ii1 = (r0 + 8) >> 4,  jj1 = (r0 + 8) & 15;
            const float* q0 = g_Q + (((long)b * 128 + wi * 16 + ii0) * 128 + wj * 16 + jj0) * 128 + h * 32;
            const float* q1 = g_Q + (((long)b * 128 + wi * 16 + ii1) * 128 + wj * 16 + jj1) * 128 + h * 32;
            #pragma unroll
            for (int kc = 0; kc < 2; kc++) {
                int d0 = kc * 16 + tg * 2;
                float2 f;
                f = *(const float2*)(q0 + d0);
                QH[mb][kc][0] = f16pack(f.x * qs, f.y * qs);
                f = *(const float2*)(q1 + d0);
                QH[mb][kc][1] = f16pack(f.x * qs, f.y * qs);
                f = *(const float2*)(q0 + d0 + 8);
                QH[mb][kc][2] = f16pack(f.x * qs, f.y * qs);
                f = *(const float2*)(q1 + d0 + 8);
                QH[mb][kc][3] = f16pack(f.x * qs, f.y * qs);
            }
        }
    }
    int qb[2];
    qb[0] = (wid + 31) * 47 + 0 * 16 + g + 31;
    qb[1] = (wid + 31) * 47 + 1 * 16 + g + 31;

    float Of[2][4][4];
    #pragma unroll
    for (int mb = 0; mb < 2; mb++)
        #pragma unroll
        for (int nd = 0; nd < 4; nd++)
            #pragma unroll
            for (int i = 0; i < 4; i++) Of[mb][nd][i] = 0.f;
    float ls[4] = {0.f, 0.f, 0.f, 0.f};

    const int kKey0 = t >> 3,        kD4 = t & 7;
    const int kKey1 = (t + 256) >> 3;
    const int vKp   = t >> 3,        vD4 = t & 7;

    __syncthreads();

    // ---- stage tile 0 (fp16) ----
    {
        #pragma unroll
        for (int it = 0; it < 2; it++) {
            int key = it == 0 ? kKey0 : kKey1;
            int u = (key >> 5), v = key & 31;
            long krow = ((long)b * 128 + rhs_s[u]) * 128 + rws_s[v];
            float4 kv = *(const float4*)(g_K + krow * 128 + h * 32 + kD4 * 4);
            KhB[key * KST + kD4 * 2]     = f16pack(kv.x, kv.y);
            KhB[key * KST + kD4 * 2 + 1] = f16pack(kv.z, kv.w);
        }
        int k0 = 2 * vKp, k1 = 2 * vKp + 1;
        long row0 = ((long)b * 128 + rhs_s[k0 >> 5]) * 128 + rws_s[k0 & 31];
        long row1 = ((long)b * 128 + rhs_s[k1 >> 5]) * 128 + rws_s[k1 & 31];
        float4 a4 = *(const float4*)(g_V + row0 * 128 + h * 32 + vD4 * 4);
        float4 c4 = *(const float4*)(g_V + row1 * 128 + h * 32 + vD4 * 4);
        const float* av = (const float*)&a4;
        const float* cv = (const float*)&c4;
        #pragma unroll
        for (int i = 0; i < 4; i++) {
            int d = vD4 * 4 + i;
            VhB[d * KST + vKp] = f16pack(av[i], cv[i]);
        }
    }
    __syncthreads();

    #pragma unroll 1
    for (int tile = 0; tile < 16; tile++) {
        const int buf  = tile & 1;
        const int nbuf = buf ^ 1;
        const bool pf  = (tile < 15);

        float4 pkA, pkB, pvA, pvB;
        if (pf) {
            int nt2 = (tile + 1) * 2;
            {
                int u = nt2 + (kKey0 >> 5), v = kKey0 & 31;
                long krow = ((long)b * 128 + rhs_s[u]) * 128 + rws_s[v];
                pkA = *(const float4*)(g_K + krow * 128 + h * 32 + kD4 * 4);
            }
            {
                int u = nt2 + (kKey1 >> 5), v = kKey1 & 31;
                long krow = ((long)b * 128 + rhs_s[u]) * 128 + rws_s[v];
                pkB = *(const float4*)(g_K + krow * 128 + h * 32 + kD4 * 4);
            }
            int k0 = 2 * vKp, k1 = 2 * vKp + 1;
            long row0 = ((long)b * 128 + rhs_s[nt2 + (k0 >> 5)]) * 128 + rws_s[k0 & 31];
            long row1 = ((long)b * 128 + rhs_s[nt2 + (k1 >> 5)]) * 128 + rws_s[k1 & 31];
            pvA = *(const float4*)(g_V + row0 * 128 + h * 32 + vD4 * 4);
            pvB = *(const float4*)(g_V + row1 * 128 + h * 32 + vD4 * 4);
        }

        const uint32_t* Kh_s = KhB + buf * 64 * KST;
        const uint32_t* Vh_s = VhB + buf * 32 * KST;

        const int tb0 = qb[0] - tile * 94 - tg * 2;
        const int tb1 = qb[1] - tile * 94 - tg * 2;

        #pragma unroll 2
        for (int nb = 0; nb < 4; nb++) {
            uint32_t KHf[2][2][2];
            #pragma unroll
            for (int j2 = 0; j2 < 2; j2++) {
                int key = (2 * nb + j2) * 8 + g;
                #pragma unroll
                for (int kc = 0; kc < 2; kc++) {
                    KHf[j2][kc][0] = Kh_s[key * KST + kc * 8 + tg];
                    KHf[j2][kc][1] = Kh_s[key * KST + kc * 8 + 4 + tg];
                }
            }
            uint32_t VHf[4][2];
            #pragma unroll
            for (int nd = 0; nd < 4; nd++) {
                int d = nd * 8 + g;
                VHf[nd][0] = Vh_s[d * KST + nb * 8 + tg];
                VHf[nd][1] = Vh_s[d * KST + nb * 8 + 4 + tg];
            }
            const int nbo = (nb >> 1) * 47 + (nb & 1) * 16;
            #pragma unroll
            for (int mb = 0; mb < 2; mb++) {
                float S0[4] = {0.f, 0.f, 0.f, 0.f};
                float S1[4] = {0.f, 0.f, 0.f, 0.f};
                #pragma unroll
                for (int kc = 0; kc < 2; kc++) {
                    mma_f16v(S0, QH[mb][kc], KHf[0][kc]);
                    mma_f16v(S1, QH[mb][kc], KHf[1][kc]);
                }
                const int bb = (mb ? tb1 : tb0) - nbo;
                const float B0  = ebias_s[bb];
                const float Bm1 = ebias_s[bb - 1];
                const float Bp8 = ebias_s[bb + 8];
                const float Bp7 = ebias_s[bb + 7];
                const float Bm8 = ebias_s[bb - 8];
                const float Bm9 = ebias_s[bb - 9];
                float p0 = ex2f(S0[0] + B0);
                float p1 = ex2f(S0[1] + Bm1);
                float p2 = ex2f(S0[2] + Bp8);
                float p3 = ex2f(S0[3] + Bp7);
                float p4 = ex2f(S1[0] + Bm8);
                float p5 = ex2f(S1[1] + Bm9);
                float p6 = ex2f(S1[2] + B0);
                float p7 = ex2f(S1[3] + Bm1);
                ls[mb * 2 + 0] += (p0 + p1) + (p4 + p5);
                ls[mb * 2 + 1] += (p2 + p3) + (p6 + p7);
                uint32_t PH[4];
                PH[0] = f16pack(p0, p1);
                PH[1] = f16pack(p2, p3);
                PH[2] = f16pack(p4, p5);
                PH[3] = f16pack(p6, p7);
                #pragma unroll
                for (int nd = 0; nd < 4; nd++)
                    mma_f16v(Of[mb][nd], PH, VHf[nd]);
            }
        }

        if (pf) {
            uint32_t* Kh = KhB + nbuf * 64 * KST;
            uint32_t* Vh = VhB + nbuf * 32 * KST;
            Kh[kKey0 * KST + kD4 * 2]     = f16pack(pkA.x, pkA.y);
            Kh[kKey0 * KST + kD4 * 2 + 1] = f16pack(pkA.z, pkA.w);
            Kh[kKey1 * KST + kD4 * 2]     = f16pack(pkB.x, pkB.y);
            Kh[kKey1 * KST + kD4 * 2 + 1] = f16pack(pkB.z, pkB.w);
            const float* av = (const float*)&pvA;
            const float* cv = (const float*)&pvB;
            #pragma unroll
            for (int i = 0; i < 4; i++) {
                int d = vD4 * 4 + i;
                Vh[d * KST + vKp] = f16pack(av[i], cv[i]);
            }
        }
        __syncthreads();
    }

    // ---- finalize ----
    #pragma unroll
    for (int i = 0; i < 4; i++) {
        ls[i] += __shfl_xor_sync(0xffffffffu, ls[i], 1);
        ls[i] += __shfl_xor_sync(0xffffffffu, ls[i], 2);
        ls[i] = 1.f / ls[i];
    }
    #pragma unroll
    for (int mb = 0; mb < 2; mb++) {
        int r0 = wid * 32 + mb * 16 + g;
        int ii0 = r0 >> 4,        jj0 = r0 & 15;
        int ii1 = (r0 + 8) >> 4,  jj1 = (r0 + 8) & 15;
        float* o0 = g_AO + (((long)b * 128 + wi * 16 + ii0) * 128 + wj * 16 + jj0) * 128 + h * 32;
        float* o1 = g_AO + (((long)b * 128 + wi * 16 + ii1) * 128 + wj * 16 + jj1) * 128 + h * 32;
        float invlo = ls[mb * 2 + 0];
        float invhi = ls[mb * 2 + 1];
        #pragma unroll
        for (int nd = 0; nd < 4; nd++) {
            float2 v;
            v.x = Of[mb][nd][0] * invlo; v.y = Of[mb][nd][1] * invlo;
            *(float2*)(o0 + nd * 8 + tg * 2) = v;
            v.x = Of[mb][nd][2] * invhi; v.y = Of[mb][nd][3] * invhi;
            *(float2*)(o1 + nd * 8 + tg * 2) = v;
        }
    }
}

// ---------------------------------------------------------------------------
extern "C" void kernel_launch(void* const* d_in, const int* in_sizes, int n_in,
                              void* d_out, int out_size)
{
    const float* x  = (const float*)d_in[0];
    const float* Wq = (const float*)d_in[1];
    const float* bq = (const float*)d_in[2];
    const float* Wk = (const float*)d_in[3];
    const float* bk = (const float*)d_in[4];
    const float* Wv = (const float*)d_in[5];
    const float* bv = (const float*)d_in[6];
    const float* Wp = (const float*)d_in[7];
    const float* bp = (const float*)d_in[8];
    const float* bt = (const float*)d_in[9];
    const int* shift = (const int*)d_in[10];
    float* out = (float*)d_out;

    cudaFuncSetAttribute(proj_qkv_kernel, cudaFuncAttributeMaxDynamicSharedMemorySize, PROJ_SMEM);
    cudaFuncSetAttribute(out_proj_kernel, cudaFuncAttributeMaxDynamicSharedMemorySize, PROJ_SMEM);
    cudaFuncSetAttribute(attn_kernel,     cudaFuncAttributeMaxDynamicSharedMemorySize, ATTN_SMEM);

    proj_qkv_kernel<<<256, 256, PROJ_SMEM>>>(x, Wq, bq, Wk, bk, Wv, bv, shift);
    attn_kernel    <<<dim3(128, 4), 256, ATTN_SMEM>>>(bt);
    out_proj_kernel<<<256, 256, PROJ_SMEM>>>(Wp, bp, shift, out);
}